// round 8
// baseline (speedup 1.0000x reference)
#include <cuda_runtime.h>
#include <cuda_fp16.h>
#include <math.h>
#include <stdint.h>

// Problem constants (fixed by the dataset)
#define B_   32
#define D_   1024
#define N_   65536
#define K_   4096
#define H_   8
#define HD_  128
#define NSPLIT 16

typedef unsigned long long u64;
typedef unsigned int       u32;

// ---------------- scratch (static device globals; no allocation) -------------
__device__ u32  g_hist16[65536];
__device__ int  g_T16;
__device__ int  g_cumAbove;
__device__ int  g_num_cand;
__device__ int  g_sel_count;
__device__ u64  g_cand[N_];
__device__ u64  g_sel_ck[K_];
__device__ int  g_sorted_idx[K_];
__device__ __half g_WkH[D_ * D_];   // W^T as fp16: [n][k]
__device__ __half g_WvH[D_ * D_];
__device__ __half g_aH[K_ * D_];    // gathered rows as fp16: [m][k]
__device__ float g_kproj[K_ * D_];
__device__ float g_vproj[K_ * D_];
__device__ float g_qproj[B_ * D_];
__device__ float g_attn[B_ * H_ * K_];
__device__ float g_ctx_part[NSPLIT * B_ * D_];
__device__ float g_ctx[B_ * D_];

// m16n8k16 fp16 MMA, fp32 accum (base PTX, sm_80+; no sm_103a-gated features)
__device__ __forceinline__ void mma_f16(
    float& c0, float& c1, float& c2, float& c3,
    u32 a0, u32 a1, u32 a2, u32 a3, u32 b0, u32 b1)
{
    asm volatile(
        "mma.sync.aligned.m16n8k16.row.col.f32.f16.f16.f32 "
        "{%0,%1,%2,%3}, {%4,%5,%6,%7}, {%8,%9}, {%0,%1,%2,%3};"
        : "+f"(c0), "+f"(c1), "+f"(c2), "+f"(c3)
        : "r"(a0), "r"(a1), "r"(a2), "r"(a3), "r"(b0), "r"(b1));
}

__device__ __forceinline__ u32 smem_u32(const void* p) {
    u32 a;
    asm("{ .reg .u64 t; cvta.to.shared.u64 t, %1; cvt.u32.u64 %0, t; }" : "=r"(a) : "l"(p));
    return a;
}
__device__ __forceinline__ void cp_async16(u32 dst, const void* src) {
    asm volatile("cp.async.ca.shared.global [%0], [%1], 16;" :: "r"(dst), "l"(src));
}
#define CP_COMMIT() asm volatile("cp.async.commit_group;" ::: "memory")
#define CP_WAIT1()  asm volatile("cp.async.wait_group 1;" ::: "memory")

// Composite key: (monotone(float) << 32) | (0xFFFFFFFF - index)
// Descending composite order == (value desc, index asc) == jax.lax.top_k order.
__device__ __forceinline__ u64 make_ck(float f, int i) {
    u32 x = __float_as_uint(f);
    u32 t = (x & 0x80000000u) ? ~x : (x | 0x80000000u);
    return ((u64)t << 32) | (u32)(0xFFFFFFFFu - (u32)i);
}

// ---------------- selection ----------------
__global__ void k_zero16() {
    int stride = gridDim.x * blockDim.x;
    for (int i = blockIdx.x * blockDim.x + threadIdx.x; i < 65536; i += stride)
        g_hist16[i] = 0;
    if (blockIdx.x == 0 && threadIdx.x == 0) { g_num_cand = 0; g_sel_count = 0; }
}

__global__ void k_hist16(const float* __restrict__ prio) {
    int stride = gridDim.x * blockDim.x;
    for (int i = blockIdx.x * blockDim.x + threadIdx.x; i < N_; i += stride) {
        u64 ck = make_ck(prio[i], i);
        atomicAdd(&g_hist16[(u32)(ck >> 48)], 1u);
    }
}

// Single CTA, 1024 threads: find the 16-bit threshold bin by descending scan.
__global__ void k_findbin() {
    __shared__ u32 strip[1024];
    int t = threadIdx.x;
    int base = 65535 - t * 64;
    u32 s = 0;
    for (int i = 0; i < 64; i++) s += g_hist16[base - i];
    strip[t] = s;
    __syncthreads();
    if (t == 0) {
        u32 cum = 0; int st = 1023;
        for (int i = 0; i < 1024; i++) {
            if (cum + strip[i] >= (u32)K_) { st = i; break; }
            cum += strip[i];
        }
        int b = 65535 - st * 64;
        for (int i = 0; i < 64; i++) {
            u32 h = g_hist16[b - i];
            if (cum + h >= (u32)K_) { g_T16 = b - i; g_cumAbove = (int)cum; break; }
            cum += h;
        }
    }
}

__global__ void k_compact16(const float* __restrict__ prio) {
    int T16 = g_T16;
    int stride = gridDim.x * blockDim.x;
    for (int i = blockIdx.x * blockDim.x + threadIdx.x; i < N_; i += stride) {
        u64 ck = make_ck(prio[i], i);
        int k16 = (int)(u32)(ck >> 48);
        if (k16 > T16) {
            int p = atomicAdd(&g_sel_count, 1);
            g_sel_ck[p] = ck;
        } else if (k16 == T16) {
            int p = atomicAdd(&g_num_cand, 1);
            g_cand[p] = ck;
        }
    }
}

// Single CTA: refine the low 48 bits among the (tiny) candidate set.
__global__ void k_selfin48() {
    __shared__ u64 sc[4096];
    __shared__ u32 hist[256];
    __shared__ u64 s_pref;
    __shared__ int s_R;
    int t = threadIdx.x;  // 256
    int nc = g_num_cand;
    bool inSm = (nc <= 4096);
    if (inSm) for (int i = t; i < nc; i += 256) sc[i] = g_cand[i];
    if (t == 0) {
        s_pref = ((u64)(u32)g_T16) << 48;
        s_R = K_ - g_cumAbove;
    }
    __syncthreads();
    for (int shift = 40; shift >= 0; shift -= 8) {
        hist[t] = 0;
        __syncthreads();
        u64 pref  = s_pref;
        u64 hmask = (~0ULL) << (shift + 8);
        for (int i = t; i < nc; i += 256) {
            u64 ck = inSm ? sc[i] : g_cand[i];
            if ((ck & hmask) == pref)
                atomicAdd(&hist[(u32)(ck >> shift) & 0xFFu], 1u);
        }
        __syncthreads();
        if (t == 0) {
            int R = s_R, cum = 0, b = 0;
            for (int bb = 255; bb >= 0; bb--) {
                if (cum + (int)hist[bb] >= R) { b = bb; break; }
                cum += (int)hist[bb];
            }
            s_pref = pref | (((u64)(u32)b) << shift);
            s_R = R - cum;
        }
        __syncthreads();
    }
    u64 T = s_pref;
    for (int i = t; i < nc; i += 256) {
        u64 ck = inSm ? sc[i] : g_cand[i];
        if (ck >= T) {
            int p = atomicAdd(&g_sel_count, 1);
            g_sel_ck[p] = ck;
        }
    }
}

// Rank sort: one warp per selected element, pairwise count of larger keys.
__global__ void k_rank() {
    __shared__ u64 s_ck[K_];  // 32 KB
    int t = threadIdx.x;
    for (int i = t; i < K_; i += blockDim.x) s_ck[i] = g_sel_ck[i];
    __syncthreads();
    int warp = t >> 5, lane = t & 31;
    int i = blockIdx.x * 8 + warp;
    u64 my = s_ck[i];
    int cnt = 0;
    for (int j = lane; j < K_; j += 32)
        cnt += (s_ck[j] > my) ? 1 : 0;
#pragma unroll
    for (int o = 16; o > 0; o >>= 1) cnt += __shfl_down_sync(0xFFFFFFFFu, cnt, o);
    if (lane == 0)
        g_sorted_idx[cnt] = (int)(0xFFFFFFFFu - (u32)(my & 0xFFFFFFFFull));
}

// ---------------- pre-convert W: fp16 transpose WT[n][k] ----------------
__global__ void k_cvtW(const float* __restrict__ Wk, const float* __restrict__ Wv) {
    __shared__ float tile[32][33];
    const float* W = blockIdx.z ? Wv : Wk;
    __half* WT     = blockIdx.z ? g_WvH : g_WkH;
    int n  = blockIdx.x * 32 + threadIdx.x;
    int k0 = blockIdx.y * 32;
    for (int i = threadIdx.y; i < 32; i += 8)
        tile[i][threadIdx.x] = W[(size_t)(k0 + i) * D_ + n];
    __syncthreads();
    int k   = k0 + threadIdx.x;
    int nn0 = blockIdx.x * 32;
    for (int i = threadIdx.y; i < 32; i += 8)
        WT[(size_t)(nn0 + i) * D_ + k] = __float2half_rn(tile[threadIdx.x][i]);
}

// ---------------- pre-gather A rows as fp16 ----------------
__global__ void k_gatherA(const float* __restrict__ buffer) {
    int row = blockIdx.x;                 // 4096
    const float4* src = (const float4*)(buffer + (size_t)g_sorted_idx[row] * D_);
    uint2* dst = (uint2*)(g_aH + (size_t)row * D_);
    int t = threadIdx.x;                  // 256
    float4 v = src[t];
    __half2 h0 = __floats2half2_rn(v.x, v.y);
    __half2 h1 = __floats2half2_rn(v.z, v.w);
    dst[t] = make_uint2(*(u32*)&h0, *(u32*)&h1);
}

// ============ K/V projection: fp16 m16n8k16 + cp.async 3-stage pipeline ======
// CTA tile 128x128, 8 warps, warp tile 64x32 (4x4 frags of 16x8), K chunks of 16.
// Stage layout (u32 words): As[128][12] then Bs[128][12]; stride 12 -> frag
// loads conflict-free (12*grp+qid mod 32 all distinct).
#define KV_CH 16
#define KV_NCH (D_ / KV_CH)        // 64
#define KV_STAGE_U32 (2 * 128 * 12)  // 3072 u32 = 12288 B
#define KV_SMEM_BYTES (3 * KV_STAGE_U32 * 4)   // 36864

__global__ void __launch_bounds__(256, 2)
k_kvproj_mma(const float* __restrict__ bk, const float* __restrict__ bv)
{
    extern __shared__ u32 dsm[];
    u32 sbase = smem_u32(dsm);

    int z  = blockIdx.z;
    const __half* WH  = z ? g_WvH : g_WkH;
    const float* bias = z ? bv : bk;
    float* out        = z ? g_vproj : g_kproj;
    int m0 = blockIdx.y * 128;
    int n0 = blockIdx.x * 128;

    int t    = threadIdx.x;
    int lane = t & 31, wid = t >> 5;
    int grp  = lane >> 2, qid = lane & 3;
    int wm   = (wid >> 2) * 64;   // 0 / 64
    int wn   = (wid & 3) * 32;    // 0 / 32 / 64 / 96

    // staging: thread t -> row = t>>1 (A-row m / B-row n), seg = t&1 (16B half)
    int row = t >> 1, seg = t & 1;
    const char* aSrc = (const char*)(g_aH + (size_t)(m0 + row) * D_) + seg * 16;
    const char* bSrc = (const char*)(WH   + (size_t)(n0 + row) * D_) + seg * 16;
    u32 dstA = sbase + (u32)(row * 48 + seg * 16);          // within-stage offsets
    u32 dstB = dstA + 128 * 48;

#define KV_ISSUE(c) do { \
    u32 _so = (u32)(((c) % 3) * (KV_STAGE_U32 * 4)); \
    cp_async16(dstA + _so, aSrc + (size_t)(c) * 32); \
    cp_async16(dstB + _so, bSrc + (size_t)(c) * 32); \
    CP_COMMIT(); \
} while (0)

    float acc[4][4][4];
#pragma unroll
    for (int i = 0; i < 4; i++)
#pragma unroll
        for (int j = 0; j < 4; j++)
#pragma unroll
            for (int q = 0; q < 4; q++) acc[i][j][q] = 0.0f;

    KV_ISSUE(0);
    KV_ISSUE(1);

    for (int c = 0; c < KV_NCH; c++) {
        CP_WAIT1();
        __syncthreads();
        if (c + 2 < KV_NCH) KV_ISSUE(c + 2);

        const u32* As = dsm + (c % 3) * KV_STAGE_U32;
        const u32* Bs = As + 128 * 12;
        u32 af[4][4], bf[4][2];
#pragma unroll
        for (int mf = 0; mf < 4; mf++) {
            int r = wm + mf * 16 + grp;
            af[mf][0] = As[r * 12 + qid];
            af[mf][1] = As[(r + 8) * 12 + qid];
            af[mf][2] = As[r * 12 + qid + 4];
            af[mf][3] = As[(r + 8) * 12 + qid + 4];
        }
#pragma unroll
        for (int nf = 0; nf < 4; nf++) {
            int n = wn + nf * 8 + grp;
            bf[nf][0] = Bs[n * 12 + qid];
            bf[nf][1] = Bs[n * 12 + qid + 4];
        }
#pragma unroll
        for (int mf = 0; mf < 4; mf++)
#pragma unroll
            for (int nf = 0; nf < 4; nf++)
                mma_f16(acc[mf][nf][0], acc[mf][nf][1], acc[mf][nf][2], acc[mf][nf][3],
                        af[mf][0], af[mf][1], af[mf][2], af[mf][3],
                        bf[nf][0], bf[nf][1]);
    }

    // epilogue: D[m][n] + bias[n]
#pragma unroll
    for (int mf = 0; mf < 4; mf++) {
#pragma unroll
        for (int nf = 0; nf < 4; nf++) {
            int n = n0 + wn + nf * 8 + 2 * qid;
            float bv0 = bias[n], bv1 = bias[n + 1];
            int r0 = m0 + wm + mf * 16 + grp;
            float2 v0 = make_float2(acc[mf][nf][0] + bv0, acc[mf][nf][1] + bv1);
            float2 v1 = make_float2(acc[mf][nf][2] + bv0, acc[mf][nf][3] + bv1);
            *(float2*)(out + (size_t)r0 * D_ + n)       = v0;
            *(float2*)(out + (size_t)(r0 + 8) * D_ + n) = v1;
        }
    }
#undef KV_ISSUE
}

// ---------------- M=32 GEMM (q proj: mode 0, out proj: mode 1) --------------
__global__ void k_gemm32(const float* __restrict__ Aext,
                         const float* __restrict__ W,
                         const float* __restrict__ bias,
                         float* __restrict__ outext, int mode)
{
    const float* A = (mode == 0) ? Aext : g_ctx;
    float* out     = (mode == 0) ? g_qproj : outext;
    int n0 = blockIdx.x * 128;

    __shared__ float As[32][36];   // [k][b]
    __shared__ float Bs[32][128];  // [k][n]
    int t = threadIdx.x;
    float acc[4][4] = {};
    int rm = (t >> 5) * 4, rn = (t & 31) * 4;
    int ab = t >> 3, akq = (t & 7) * 4;

    for (int k0 = 0; k0 < D_; k0 += 32) {
        float4 av = *(const float4*)(A + (size_t)ab * D_ + k0 + akq);
        As[akq+0][ab]=av.x; As[akq+1][ab]=av.y; As[akq+2][ab]=av.z; As[akq+3][ab]=av.w;
#pragma unroll
        for (int p = 0; p < 4; p++) {
            int id = t + p * 256;
            int br = id >> 5, bc = (id & 31) * 4;
            *(float4*)&Bs[br][bc] = *(const float4*)(W + (size_t)(k0 + br) * D_ + n0 + bc);
        }
        __syncthreads();
#pragma unroll
        for (int kk = 0; kk < 32; kk++) {
            float a[4], b[4];
            *(float4*)&a[0] = *(const float4*)&As[kk][rm];
            *(float4*)&b[0] = *(const float4*)&Bs[kk][rn];
#pragma unroll
            for (int i = 0; i < 4; i++)
#pragma unroll
                for (int j = 0; j < 4; j++)
                    acc[i][j] += a[i] * b[j];
        }
        __syncthreads();
    }
#pragma unroll
    for (int i = 0; i < 4; i++) {
        float* op = out + (size_t)(rm + i) * D_ + n0 + rn;
#pragma unroll
        for (int j = 0; j < 4; j++)
            op[j] = acc[i][j] + bias[n0 + rn + j];
    }
}

// ---------------- scores[b,h,j] = scale * q[b,h,:] . k[j,h,:] ---------------
__global__ void k_scores() {
    int j0 = blockIdx.x * 128;
    int h  = blockIdx.y;
    __shared__ float As[32][36];   // [d][b]
    __shared__ float Bs[32][132];  // [d][j]
    int t = threadIdx.x;
    float acc[4][4] = {};
    int rm = (t >> 5) * 4, rn = (t & 31) * 4;
    int ab = t >> 3, akq = (t & 7) * 4;

    for (int d0 = 0; d0 < HD_; d0 += 32) {
        float4 av = *(const float4*)(g_qproj + (size_t)ab * D_ + h * HD_ + d0 + akq);
        As[akq+0][ab]=av.x; As[akq+1][ab]=av.y; As[akq+2][ab]=av.z; As[akq+3][ab]=av.w;
#pragma unroll
        for (int p = 0; p < 4; p++) {
            int id = t + p * 256;
            int jr = id >> 3, dq = (id & 7) * 4;
            float4 bvv = *(const float4*)(g_kproj + (size_t)(j0 + jr) * D_ + h * HD_ + d0 + dq);
            Bs[dq+0][jr]=bvv.x; Bs[dq+1][jr]=bvv.y; Bs[dq+2][jr]=bvv.z; Bs[dq+3][jr]=bvv.w;
        }
        __syncthreads();
#pragma unroll
        for (int kk = 0; kk < 32; kk++) {
            float a[4], b[4];
            *(float4*)&a[0] = *(const float4*)&As[kk][rm];
            *(float4*)&b[0] = *(const float4*)&Bs[kk][rn];
#pragma unroll
            for (int i = 0; i < 4; i++)
#pragma unroll
                for (int j = 0; j < 4; j++)
                    acc[i][j] += a[i] * b[j];
        }
        __syncthreads();
    }
    const float scale = 0.08838834764831845f;  // 128^-0.5
#pragma unroll
    for (int i = 0; i < 4; i++)
#pragma unroll
        for (int j = 0; j < 4; j++)
            g_attn[((size_t)(rm + i) * H_ + h) * K_ + j0 + rn + j] = acc[i][j] * scale;
}

// ---------------- softmax over j (in place), one CTA per (b,h) row ----------
__global__ void k_softmax() {
    int row = blockIdx.x;
    float* p = g_attn + (size_t)row * K_;
    __shared__ float sd[K_];
    __shared__ float red[256];
    int t = threadIdx.x;
    float mx = -1e30f;
    for (int i = t; i < K_; i += 256) { float v = p[i]; sd[i] = v; mx = fmaxf(mx, v); }
    red[t] = mx; __syncthreads();
    for (int o = 128; o > 0; o >>= 1) { if (t < o) red[t] = fmaxf(red[t], red[t + o]); __syncthreads(); }
    mx = red[0]; __syncthreads();
    float sum = 0.0f;
    for (int i = t; i < K_; i += 256) { float e = expf(sd[i] - mx); sd[i] = e; sum += e; }
    red[t] = sum; __syncthreads();
    for (int o = 128; o > 0; o >>= 1) { if (t < o) red[t] += red[t + o]; __syncthreads(); }
    float inv = 1.0f / red[0];
    for (int i = t; i < K_; i += 256) p[i] = sd[i] * inv;
}

// ---------------- attn_avg = mean over heads -> d_out[32768:] ---------------
__global__ void k_avg(float* __restrict__ out2) {
    int idx = blockIdx.x * blockDim.x + threadIdx.x;  // 131072 total
    int b = idx >> 12, j = idx & 4095;
    float s = 0.0f;
#pragma unroll
    for (int h = 0; h < H_; h++) s += g_attn[((size_t)b * H_ + h) * K_ + j];
    out2[(size_t)b * K_ + j] = s * 0.125f;
}

// ---------------- ctx partials: attn[b,h,:] @ v[:,h,:] over j-split ---------
__global__ void k_ctxpart() {
    int h  = blockIdx.x;       // 8
    int sp = blockIdx.y;       // 16
    int jbase = sp * (K_ / NSPLIT);   // 256 j per split
    __shared__ float As[32][36];    // [j][b]
    __shared__ float Bs[32][128];   // [j][d]
    int t = threadIdx.x;
    float acc[4][4] = {};
    int rm = (t >> 5) * 4, rn = (t & 31) * 4;
    int ab = t >> 3, ajq = (t & 7) * 4;

    for (int k0 = 0; k0 < K_ / NSPLIT; k0 += 32) {
        float4 av = *(const float4*)(g_attn + ((size_t)ab * H_ + h) * K_ + jbase + k0 + ajq);
        As[ajq+0][ab]=av.x; As[ajq+1][ab]=av.y; As[ajq+2][ab]=av.z; As[ajq+3][ab]=av.w;
#pragma unroll
        for (int p = 0; p < 4; p++) {
            int id = t + p * 256;
            int jr = id >> 5, dc = (id & 31) * 4;
            *(float4*)&Bs[jr][dc] =
                *(const float4*)(g_vproj + (size_t)(jbase + k0 + jr) * D_ + h * HD_ + dc);
        }
        __syncthreads();
#pragma unroll
        for (int kk = 0; kk < 32; kk++) {
            float a[4], b[4];
            *(float4*)&a[0] = *(const float4*)&As[kk][rm];
            *(float4*)&b[0] = *(const float4*)&Bs[kk][rn];
#pragma unroll
            for (int i = 0; i < 4; i++)
#pragma unroll
                for (int j = 0; j < 4; j++)
                    acc[i][j] += a[i] * b[j];
        }
        __syncthreads();
    }
#pragma unroll
    for (int i = 0; i < 4; i++)
#pragma unroll
        for (int j = 0; j < 4; j++)
            g_ctx_part[((size_t)sp * B_ + rm + i) * D_ + h * HD_ + rn + j] = acc[i][j];
}

__global__ void k_ctxred() {
    int i = blockIdx.x * blockDim.x + threadIdx.x;  // 32768
    float s = 0.0f;
#pragma unroll
    for (int sp = 0; sp < NSPLIT; sp++) s += g_ctx_part[(size_t)sp * B_ * D_ + i];
    g_ctx[i] = s;
}

// ---------------- launch ----------------
extern "C" void kernel_launch(void* const* d_in, const int* in_sizes, int n_in,
                              void* d_out, int out_size) {
    const float* query  = (const float*)d_in[0];
    const float* buffer = (const float*)d_in[1];
    const float* prio   = (const float*)d_in[2];
    const float* Wq     = (const float*)d_in[3];
    const float* bq     = (const float*)d_in[4];
    const float* Wk     = (const float*)d_in[5];
    const float* bk     = (const float*)d_in[6];
    const float* Wv     = (const float*)d_in[7];
    const float* bv     = (const float*)d_in[8];
    const float* Wo     = (const float*)d_in[9];
    const float* bo     = (const float*)d_in[10];
    float* out = (float*)d_out;   // [0,32768): retrieved, [32768,163840): attn_avg

    // selection + weight pre-convert (cvtW independent of selection)
    k_zero16<<<64, 256>>>();
    k_hist16<<<64, 256>>>(prio);
    k_cvtW<<<dim3(32, 32, 2), dim3(32, 8)>>>(Wk, Wv);
    k_findbin<<<1, 1024>>>();
    k_compact16<<<64, 256>>>(prio);
    k_selfin48<<<1, 256>>>();
    k_rank<<<K_ / 8, 256>>>();
    k_gatherA<<<K_, 256>>>(buffer);

    // K/V projection on tensor cores (fp16 mma, cp.async 3-stage pipeline)
    k_kvproj_mma<<<dim3(8, 32, 2), 256, KV_SMEM_BYTES>>>(bk, bv);

    // attention tail
    k_gemm32<<<8, 256>>>(query, Wq, bq, nullptr, 0);       // q projection
    k_scores<<<dim3(32, 8), 256>>>();
    k_softmax<<<256, 256>>>();
    k_avg<<<512, 256>>>(out + B_ * D_);
    k_ctxpart<<<dim3(8, NSPLIT), 256>>>();
    k_ctxred<<<128, 256>>>();
    k_gemm32<<<8, 256>>>(nullptr, Wo, bo, out, 1);         // output projection
}

// round 9
// speedup vs baseline: 1.0850x; 1.0850x over previous
#include <cuda_runtime.h>
#include <cuda_fp16.h>
#include <math.h>
#include <stdint.h>

// Problem constants (fixed by the dataset)
#define B_   32
#define D_   1024
#define N_   65536
#define K_   4096
#define H_   8
#define HD_  128
#define NSPLIT 16

typedef unsigned long long u64;
typedef unsigned int       u32;

// ---------------- scratch (static device globals; no allocation) -------------
__device__ u32  g_hist16[65536];
__device__ int  g_T16;
__device__ int  g_cumAbove;
__device__ int  g_num_cand;
__device__ int  g_sel_count;
__device__ u64  g_cand[N_];
__device__ u64  g_sel_ck[K_];
__device__ int  g_sorted_idx[K_];
__device__ __half g_WkH[D_ * D_];   // W^T as fp16: [n][k]
__device__ __half g_WvH[D_ * D_];
__device__ __half g_aH[K_ * D_];    // gathered rows as fp16: [m][k]
__device__ float g_kproj[K_ * D_];
__device__ float g_vproj[K_ * D_];
__device__ float g_qproj[B_ * D_];
__device__ float g_attn[B_ * H_ * K_];
__device__ float g_ctx_part[NSPLIT * B_ * D_];
__device__ float g_ctx[B_ * D_];

// m16n8k16 fp16 MMA, fp32 accum (base PTX, sm_80+; no sm_103a-gated features)
__device__ __forceinline__ void mma_f16(
    float& c0, float& c1, float& c2, float& c3,
    u32 a0, u32 a1, u32 a2, u32 a3, u32 b0, u32 b1)
{
    asm volatile(
        "mma.sync.aligned.m16n8k16.row.col.f32.f16.f16.f32 "
        "{%0,%1,%2,%3}, {%4,%5,%6,%7}, {%8,%9}, {%0,%1,%2,%3};"
        : "+f"(c0), "+f"(c1), "+f"(c2), "+f"(c3)
        : "r"(a0), "r"(a1), "r"(a2), "r"(a3), "r"(b0), "r"(b1));
}

__device__ __forceinline__ u32 smem_u32(const void* p) {
    u32 a;
    asm("{ .reg .u64 t; cvta.to.shared.u64 t, %1; cvt.u32.u64 %0, t; }" : "=r"(a) : "l"(p));
    return a;
}
__device__ __forceinline__ void cp_async16(u32 dst, const void* src) {
    asm volatile("cp.async.ca.shared.global [%0], [%1], 16;" :: "r"(dst), "l"(src));
}
#define CP_COMMIT() asm volatile("cp.async.commit_group;" ::: "memory")
#define CP_WAIT1()  asm volatile("cp.async.wait_group 1;" ::: "memory")

// Composite key: (monotone(float) << 32) | (0xFFFFFFFF - index)
// Descending composite order == (value desc, index asc) == jax.lax.top_k order.
__device__ __forceinline__ u64 make_ck(float f, int i) {
    u32 x = __float_as_uint(f);
    u32 t = (x & 0x80000000u) ? ~x : (x | 0x80000000u);
    return ((u64)t << 32) | (u32)(0xFFFFFFFFu - (u32)i);
}

// ---------------- selection ----------------
__global__ void k_zero16() {
    int stride = gridDim.x * blockDim.x;
    for (int i = blockIdx.x * blockDim.x + threadIdx.x; i < 65536; i += stride)
        g_hist16[i] = 0;
    if (blockIdx.x == 0 && threadIdx.x == 0) { g_num_cand = 0; g_sel_count = 0; }
}

__global__ void k_hist16(const float* __restrict__ prio) {
    int stride = gridDim.x * blockDim.x;
    for (int i = blockIdx.x * blockDim.x + threadIdx.x; i < N_; i += stride) {
        u64 ck = make_ck(prio[i], i);
        atomicAdd(&g_hist16[(u32)(ck >> 48)], 1u);
    }
}

// Single CTA, 1024 threads: find the 16-bit threshold bin. Fully parallel:
// vectorized strip sums + Hillis-Steele scan + parallel boundary pick.
__global__ void k_findbin() {
    __shared__ u32 strip[1024];
    __shared__ u32 arr[64];
    __shared__ int s_st;
    __shared__ u32 s_cum;
    int t = threadIdx.x;

    // strip[t] = sum of bins [65536-64(t+1), 65535-64t]  (descending strips)
    {
        const uint4* p = (const uint4*)(g_hist16 + (65536 - 64 * (t + 1)));
        u32 s = 0;
#pragma unroll
        for (int i = 0; i < 16; i++) { uint4 v = p[i]; s += v.x + v.y + v.z + v.w; }
        strip[t] = s;
    }
    __syncthreads();

    // inclusive prefix sum over strips (index order = descending bins)
    for (int off = 1; off < 1024; off <<= 1) {
        u32 v = strip[t];
        u32 a = (t >= off) ? strip[t - off] : 0u;
        __syncthreads();
        strip[t] = v + a;
        __syncthreads();
    }

    // boundary strip: first t with prefix >= K
    {
        u32 inc  = strip[t];
        u32 prev = (t == 0) ? 0u : strip[t - 1];
        if (inc >= (u32)K_ && prev < (u32)K_) { s_st = t; s_cum = prev; }
    }
    __syncthreads();

    int st = s_st;
    u32 cum = s_cum;
    // refine within strip: arr[i] = bin (65535 - 64*st - i), descending
    if (t < 64) arr[t] = g_hist16[65535 - 64 * st - t];
    __syncthreads();
    for (int off = 1; off < 64; off <<= 1) {
        u32 v = (t < 64) ? arr[t] : 0u;
        u32 a = (t < 64 && t >= off) ? arr[t - off] : 0u;
        __syncthreads();
        if (t < 64) arr[t] = v + a;
        __syncthreads();
    }
    if (t < 64) {
        u32 R    = (u32)K_ - cum;
        u32 inc  = arr[t];
        u32 prev = (t == 0) ? 0u : arr[t - 1];
        if (inc >= R && prev < R) {
            g_T16 = 65535 - 64 * st - t;
            g_cumAbove = (int)(cum + prev);
        }
    }
}

__global__ void k_compact16(const float* __restrict__ prio) {
    int T16 = g_T16;
    int stride = gridDim.x * blockDim.x;
    for (int i = blockIdx.x * blockDim.x + threadIdx.x; i < N_; i += stride) {
        u64 ck = make_ck(prio[i], i);
        int k16 = (int)(u32)(ck >> 48);
        if (k16 > T16) {
            int p = atomicAdd(&g_sel_count, 1);
            g_sel_ck[p] = ck;
        } else if (k16 == T16) {
            int p = atomicAdd(&g_num_cand, 1);
            g_cand[p] = ck;
        }
    }
}

// Single CTA: refine the low 48 bits among the (tiny) candidate set.
__global__ void k_selfin48() {
    __shared__ u64 sc[4096];
    __shared__ u32 hist[256];
    __shared__ u64 s_pref;
    __shared__ int s_R;
    int t = threadIdx.x;  // 256
    int nc = g_num_cand;
    bool inSm = (nc <= 4096);
    if (inSm) for (int i = t; i < nc; i += 256) sc[i] = g_cand[i];
    if (t == 0) {
        s_pref = ((u64)(u32)g_T16) << 48;
        s_R = K_ - g_cumAbove;
    }
    __syncthreads();
    for (int shift = 40; shift >= 0; shift -= 8) {
        hist[t] = 0;
        __syncthreads();
        u64 pref  = s_pref;
        u64 hmask = (~0ULL) << (shift + 8);
        for (int i = t; i < nc; i += 256) {
            u64 ck = inSm ? sc[i] : g_cand[i];
            if ((ck & hmask) == pref)
                atomicAdd(&hist[(u32)(ck >> shift) & 0xFFu], 1u);
        }
        __syncthreads();
        if (t == 0) {
            int R = s_R, cum = 0, b = 0;
            for (int bb = 255; bb >= 0; bb--) {
                if (cum + (int)hist[bb] >= R) { b = bb; break; }
                cum += (int)hist[bb];
            }
            s_pref = pref | (((u64)(u32)b) << shift);
            s_R = R - cum;
        }
        __syncthreads();
    }
    u64 T = s_pref;
    for (int i = t; i < nc; i += 256) {
        u64 ck = inSm ? sc[i] : g_cand[i];
        if (ck >= T) {
            int p = atomicAdd(&g_sel_count, 1);
            g_sel_ck[p] = ck;
        }
    }
}

// Rank sort: one warp per selected element, pairwise count of larger keys.
__global__ void k_rank() {
    __shared__ u64 s_ck[K_];  // 32 KB
    int t = threadIdx.x;
    for (int i = t; i < K_; i += blockDim.x) s_ck[i] = g_sel_ck[i];
    __syncthreads();
    int warp = t >> 5, lane = t & 31;
    int i = blockIdx.x * 8 + warp;
    u64 my = s_ck[i];
    int cnt = 0;
    for (int j = lane; j < K_; j += 32)
        cnt += (s_ck[j] > my) ? 1 : 0;
#pragma unroll
    for (int o = 16; o > 0; o >>= 1) cnt += __shfl_down_sync(0xFFFFFFFFu, cnt, o);
    if (lane == 0)
        g_sorted_idx[cnt] = (int)(0xFFFFFFFFu - (u32)(my & 0xFFFFFFFFull));
}

// ---------------- pre-convert W: fp16 transpose WT[n][k] ----------------
__global__ void k_cvtW(const float* __restrict__ Wk, const float* __restrict__ Wv) {
    __shared__ float tile[32][33];
    const float* W = blockIdx.z ? Wv : Wk;
    __half* WT     = blockIdx.z ? g_WvH : g_WkH;
    int n  = blockIdx.x * 32 + threadIdx.x;
    int k0 = blockIdx.y * 32;
    for (int i = threadIdx.y; i < 32; i += 8)
        tile[i][threadIdx.x] = W[(size_t)(k0 + i) * D_ + n];
    __syncthreads();
    int k   = k0 + threadIdx.x;
    int nn0 = blockIdx.x * 32;
    for (int i = threadIdx.y; i < 32; i += 8)
        WT[(size_t)(nn0 + i) * D_ + k] = __float2half_rn(tile[threadIdx.x][i]);
}

// ---------------- pre-gather A rows as fp16 ----------------
__global__ void k_gatherA(const float* __restrict__ buffer) {
    int row = blockIdx.x;                 // 4096
    const float4* src = (const float4*)(buffer + (size_t)g_sorted_idx[row] * D_);
    uint2* dst = (uint2*)(g_aH + (size_t)row * D_);
    int t = threadIdx.x;                  // 256
    float4 v = src[t];
    __half2 h0 = __floats2half2_rn(v.x, v.y);
    __half2 h1 = __floats2half2_rn(v.z, v.w);
    dst[t] = make_uint2(*(u32*)&h0, *(u32*)&h1);
}

// ============ K/V projection: fp16 m16n8k16 + cp.async 3-stage pipeline ======
// CTA tile 128x128, 8 warps, warp tile 64x32 (4x4 frags of 16x8), K chunks of 16.
// Stage layout (u32 words): As[128][12] then Bs[128][12]; stride 12 -> frag
// loads conflict-free (12*grp+qid mod 32 all distinct).
#define KV_CH 16
#define KV_NCH (D_ / KV_CH)        // 64
#define KV_STAGE_U32 (2 * 128 * 12)  // 3072 u32 = 12288 B
#define KV_SMEM_BYTES (3 * KV_STAGE_U32 * 4)   // 36864

__global__ void __launch_bounds__(256, 2)
k_kvproj_mma(const float* __restrict__ bk, const float* __restrict__ bv)
{
    extern __shared__ u32 dsm[];
    u32 sbase = smem_u32(dsm);

    int z  = blockIdx.z;
    const __half* WH  = z ? g_WvH : g_WkH;
    const float* bias = z ? bv : bk;
    float* out        = z ? g_vproj : g_kproj;
    int m0 = blockIdx.y * 128;
    int n0 = blockIdx.x * 128;

    int t    = threadIdx.x;
    int lane = t & 31, wid = t >> 5;
    int grp  = lane >> 2, qid = lane & 3;
    int wm   = (wid >> 2) * 64;   // 0 / 64
    int wn   = (wid & 3) * 32;    // 0 / 32 / 64 / 96

    // staging: thread t -> row = t>>1 (A-row m / B-row n), seg = t&1 (16B half)
    int row = t >> 1, seg = t & 1;
    const char* aSrc = (const char*)(g_aH + (size_t)(m0 + row) * D_) + seg * 16;
    const char* bSrc = (const char*)(WH   + (size_t)(n0 + row) * D_) + seg * 16;
    u32 dstA = sbase + (u32)(row * 48 + seg * 16);          // within-stage offsets
    u32 dstB = dstA + 128 * 48;

#define KV_ISSUE(c) do { \
    u32 _so = (u32)(((c) % 3) * (KV_STAGE_U32 * 4)); \
    cp_async16(dstA + _so, aSrc + (size_t)(c) * 32); \
    cp_async16(dstB + _so, bSrc + (size_t)(c) * 32); \
    CP_COMMIT(); \
} while (0)

    float acc[4][4][4];
#pragma unroll
    for (int i = 0; i < 4; i++)
#pragma unroll
        for (int j = 0; j < 4; j++)
#pragma unroll
            for (int q = 0; q < 4; q++) acc[i][j][q] = 0.0f;

    KV_ISSUE(0);
    KV_ISSUE(1);

    for (int c = 0; c < KV_NCH; c++) {
        CP_WAIT1();
        __syncthreads();
        if (c + 2 < KV_NCH) KV_ISSUE(c + 2);

        const u32* As = dsm + (c % 3) * KV_STAGE_U32;
        const u32* Bs = As + 128 * 12;
        u32 af[4][4], bf[4][2];
#pragma unroll
        for (int mf = 0; mf < 4; mf++) {
            int r = wm + mf * 16 + grp;
            af[mf][0] = As[r * 12 + qid];
            af[mf][1] = As[(r + 8) * 12 + qid];
            af[mf][2] = As[r * 12 + qid + 4];
            af[mf][3] = As[(r + 8) * 12 + qid + 4];
        }
#pragma unroll
        for (int nf = 0; nf < 4; nf++) {
            int n = wn + nf * 8 + grp;
            bf[nf][0] = Bs[n * 12 + qid];
            bf[nf][1] = Bs[n * 12 + qid + 4];
        }
#pragma unroll
        for (int mf = 0; mf < 4; mf++)
#pragma unroll
            for (int nf = 0; nf < 4; nf++)
                mma_f16(acc[mf][nf][0], acc[mf][nf][1], acc[mf][nf][2], acc[mf][nf][3],
                        af[mf][0], af[mf][1], af[mf][2], af[mf][3],
                        bf[nf][0], bf[nf][1]);
    }

    // epilogue: D[m][n] + bias[n]
#pragma unroll
    for (int mf = 0; mf < 4; mf++) {
#pragma unroll
        for (int nf = 0; nf < 4; nf++) {
            int n = n0 + wn + nf * 8 + 2 * qid;
            float bv0 = bias[n], bv1 = bias[n + 1];
            int r0 = m0 + wm + mf * 16 + grp;
            float2 v0 = make_float2(acc[mf][nf][0] + bv0, acc[mf][nf][1] + bv1);
            float2 v1 = make_float2(acc[mf][nf][2] + bv0, acc[mf][nf][3] + bv1);
            *(float2*)(out + (size_t)r0 * D_ + n)       = v0;
            *(float2*)(out + (size_t)(r0 + 8) * D_ + n) = v1;
        }
    }
#undef KV_ISSUE
}

// ---------------- M=32 GEMM (q proj: mode 0, out proj: mode 1) --------------
__global__ void k_gemm32(const float* __restrict__ Aext,
                         const float* __restrict__ W,
                         const float* __restrict__ bias,
                         float* __restrict__ outext, int mode)
{
    const float* A = (mode == 0) ? Aext : g_ctx;
    float* out     = (mode == 0) ? g_qproj : outext;
    int n0 = blockIdx.x * 128;

    __shared__ float As[32][36];   // [k][b]
    __shared__ float Bs[32][128];  // [k][n]
    int t = threadIdx.x;
    float acc[4][4] = {};
    int rm = (t >> 5) * 4, rn = (t & 31) * 4;
    int ab = t >> 3, akq = (t & 7) * 4;

    for (int k0 = 0; k0 < D_; k0 += 32) {
        float4 av = *(const float4*)(A + (size_t)ab * D_ + k0 + akq);
        As[akq+0][ab]=av.x; As[akq+1][ab]=av.y; As[akq+2][ab]=av.z; As[akq+3][ab]=av.w;
#pragma unroll
        for (int p = 0; p < 4; p++) {
            int id = t + p * 256;
            int br = id >> 5, bc = (id & 31) * 4;
            *(float4*)&Bs[br][bc] = *(const float4*)(W + (size_t)(k0 + br) * D_ + n0 + bc);
        }
        __syncthreads();
#pragma unroll
        for (int kk = 0; kk < 32; kk++) {
            float a[4], b[4];
            *(float4*)&a[0] = *(const float4*)&As[kk][rm];
            *(float4*)&b[0] = *(const float4*)&Bs[kk][rn];
#pragma unroll
            for (int i = 0; i < 4; i++)
#pragma unroll
                for (int j = 0; j < 4; j++)
                    acc[i][j] += a[i] * b[j];
        }
        __syncthreads();
    }
#pragma unroll
    for (int i = 0; i < 4; i++) {
        float* op = out + (size_t)(rm + i) * D_ + n0 + rn;
#pragma unroll
        for (int j = 0; j < 4; j++)
            op[j] = acc[i][j] + bias[n0 + rn + j];
    }
}

// ---------------- scores[b,h,j] = scale * q[b,h,:] . k[j,h,:] ---------------
__global__ void k_scores() {
    int j0 = blockIdx.x * 128;
    int h  = blockIdx.y;
    __shared__ float As[32][36];   // [d][b]
    __shared__ float Bs[32][132];  // [d][j]
    int t = threadIdx.x;
    float acc[4][4] = {};
    int rm = (t >> 5) * 4, rn = (t & 31) * 4;
    int ab = t >> 3, akq = (t & 7) * 4;

    for (int d0 = 0; d0 < HD_; d0 += 32) {
        float4 av = *(const float4*)(g_qproj + (size_t)ab * D_ + h * HD_ + d0 + akq);
        As[akq+0][ab]=av.x; As[akq+1][ab]=av.y; As[akq+2][ab]=av.z; As[akq+3][ab]=av.w;
#pragma unroll
        for (int p = 0; p < 4; p++) {
            int id = t + p * 256;
            int jr = id >> 3, dq = (id & 7) * 4;
            float4 bvv = *(const float4*)(g_kproj + (size_t)(j0 + jr) * D_ + h * HD_ + d0 + dq);
            Bs[dq+0][jr]=bvv.x; Bs[dq+1][jr]=bvv.y; Bs[dq+2][jr]=bvv.z; Bs[dq+3][jr]=bvv.w;
        }
        __syncthreads();
#pragma unroll
        for (int kk = 0; kk < 32; kk++) {
            float a[4], b[4];
            *(float4*)&a[0] = *(const float4*)&As[kk][rm];
            *(float4*)&b[0] = *(const float4*)&Bs[kk][rn];
#pragma unroll
            for (int i = 0; i < 4; i++)
#pragma unroll
                for (int j = 0; j < 4; j++)
                    acc[i][j] += a[i] * b[j];
        }
        __syncthreads();
    }
    const float scale = 0.08838834764831845f;  // 128^-0.5
#pragma unroll
    for (int i = 0; i < 4; i++)
#pragma unroll
        for (int j = 0; j < 4; j++)
            g_attn[((size_t)(rm + i) * H_ + h) * K_ + j0 + rn + j] = acc[i][j] * scale;
}

// ---------------- softmax over j (in place), one CTA per (b,h) row ----------
__global__ void k_softmax() {
    int row = blockIdx.x;
    float* p = g_attn + (size_t)row * K_;
    __shared__ float sd[K_];
    __shared__ float red[256];
    int t = threadIdx.x;
    float mx = -1e30f;
    for (int i = t; i < K_; i += 256) { float v = p[i]; sd[i] = v; mx = fmaxf(mx, v); }
    red[t] = mx; __syncthreads();
    for (int o = 128; o > 0; o >>= 1) { if (t < o) red[t] = fmaxf(red[t], red[t + o]); __syncthreads(); }
    mx = red[0]; __syncthreads();
    float sum = 0.0f;
    for (int i = t; i < K_; i += 256) { float e = expf(sd[i] - mx); sd[i] = e; sum += e; }
    red[t] = sum; __syncthreads();
    for (int o = 128; o > 0; o >>= 1) { if (t < o) red[t] += red[t + o]; __syncthreads(); }
    float inv = 1.0f / red[0];
    for (int i = t; i < K_; i += 256) p[i] = sd[i] * inv;
}

// ---------------- attn_avg = mean over heads -> d_out[32768:] ---------------
__global__ void k_avg(float* __restrict__ out2) {
    int idx = blockIdx.x * blockDim.x + threadIdx.x;  // 131072 total
    int b = idx >> 12, j = idx & 4095;
    float s = 0.0f;
#pragma unroll
    for (int h = 0; h < H_; h++) s += g_attn[((size_t)b * H_ + h) * K_ + j];
    out2[(size_t)b * K_ + j] = s * 0.125f;
}

// ---------------- ctx partials: attn[b,h,:] @ v[:,h,:] over j-split ---------
__global__ void k_ctxpart() {
    int h  = blockIdx.x;       // 8
    int sp = blockIdx.y;       // 16
    int jbase = sp * (K_ / NSPLIT);   // 256 j per split
    __shared__ float As[32][36];    // [j][b]
    __shared__ float Bs[32][128];   // [j][d]
    int t = threadIdx.x;
    float acc[4][4] = {};
    int rm = (t >> 5) * 4, rn = (t & 31) * 4;
    int ab = t >> 3, ajq = (t & 7) * 4;

    for (int k0 = 0; k0 < K_ / NSPLIT; k0 += 32) {
        float4 av = *(const float4*)(g_attn + ((size_t)ab * H_ + h) * K_ + jbase + k0 + ajq);
        As[ajq+0][ab]=av.x; As[ajq+1][ab]=av.y; As[ajq+2][ab]=av.z; As[ajq+3][ab]=av.w;
#pragma unroll
        for (int p = 0; p < 4; p++) {
            int id = t + p * 256;
            int jr = id >> 5, dc = (id & 31) * 4;
            *(float4*)&Bs[jr][dc] =
                *(const float4*)(g_vproj + (size_t)(jbase + k0 + jr) * D_ + h * HD_ + dc);
        }
        __syncthreads();
#pragma unroll
        for (int kk = 0; kk < 32; kk++) {
            float a[4], b[4];
            *(float4*)&a[0] = *(const float4*)&As[kk][rm];
            *(float4*)&b[0] = *(const float4*)&Bs[kk][rn];
#pragma unroll
            for (int i = 0; i < 4; i++)
#pragma unroll
                for (int j = 0; j < 4; j++)
                    acc[i][j] += a[i] * b[j];
        }
        __syncthreads();
    }
#pragma unroll
    for (int i = 0; i < 4; i++)
#pragma unroll
        for (int j = 0; j < 4; j++)
            g_ctx_part[((size_t)sp * B_ + rm + i) * D_ + h * HD_ + rn + j] = acc[i][j];
}

__global__ void k_ctxred() {
    int i = blockIdx.x * blockDim.x + threadIdx.x;  // 32768
    float s = 0.0f;
#pragma unroll
    for (int sp = 0; sp < NSPLIT; sp++) s += g_ctx_part[(size_t)sp * B_ * D_ + i];
    g_ctx[i] = s;
}

// ---------------- launch ----------------
extern "C" void kernel_launch(void* const* d_in, const int* in_sizes, int n_in,
                              void* d_out, int out_size) {
    const float* query  = (const float*)d_in[0];
    const float* buffer = (const float*)d_in[1];
    const float* prio   = (const float*)d_in[2];
    const float* Wq     = (const float*)d_in[3];
    const float* bq     = (const float*)d_in[4];
    const float* Wk     = (const float*)d_in[5];
    const float* bk     = (const float*)d_in[6];
    const float* Wv     = (const float*)d_in[7];
    const float* bv     = (const float*)d_in[8];
    const float* Wo     = (const float*)d_in[9];
    const float* bo     = (const float*)d_in[10];
    float* out = (float*)d_out;   // [0,32768): retrieved, [32768,163840): attn_avg

    // selection + weight pre-convert (cvtW independent of selection)
    k_zero16<<<64, 256>>>();
    k_hist16<<<64, 256>>>(prio);
    k_cvtW<<<dim3(32, 32, 2), dim3(32, 8)>>>(Wk, Wv);
    k_findbin<<<1, 1024>>>();
    k_compact16<<<64, 256>>>(prio);
    k_selfin48<<<1, 256>>>();
    k_rank<<<K_ / 8, 256>>>();
    k_gatherA<<<K_, 256>>>(buffer);

    // K/V projection on tensor cores (fp16 mma, cp.async 3-stage pipeline)
    k_kvproj_mma<<<dim3(8, 32, 2), 256, KV_SMEM_BYTES>>>(bk, bv);

    // attention tail
    k_gemm32<<<8, 256>>>(query, Wq, bq, nullptr, 0);       // q projection
    k_scores<<<dim3(32, 8), 256>>>();
    k_softmax<<<256, 256>>>();
    k_avg<<<512, 256>>>(out + B_ * D_);
    k_ctxpart<<<dim3(8, NSPLIT), 256>>>();
    k_ctxred<<<128, 256>>>();
    k_gemm32<<<8, 256>>>(nullptr, Wo, bo, out, 1);         // output projection
}

// round 11
// speedup vs baseline: 1.4999x; 1.3824x over previous
#include <cuda_runtime.h>
#include <cuda_fp16.h>
#include <math.h>
#include <stdint.h>

// Problem constants (fixed by the dataset)
#define B_   32
#define D_   1024
#define N_   65536
#define K_   4096
#define H_   8
#define HD_  128
#define NSPLIT 16
#define GSPLIT 4

typedef unsigned long long u64;
typedef unsigned int       u32;

// ---------------- scratch (static device globals; no allocation) -------------
__device__ u32  g_hist16[65536];
__device__ u32  g_strip[1024];      // coarse histogram: bin >> 6
__device__ int  g_T16;
__device__ int  g_cumAbove;
__device__ int  g_num_cand;
__device__ int  g_sel_count;
__device__ u64  g_cand[N_];
__device__ u64  g_sel_ck[K_];
__device__ int  g_sorted_idx[K_];
__device__ __half g_WkH[D_ * D_];   // W^T as fp16: [n][k]
__device__ __half g_WvH[D_ * D_];
__device__ __half g_aH[K_ * D_];    // gathered rows as fp16: [m][k]
__device__ float g_kproj[K_ * D_];
__device__ float g_vproj[K_ * D_];
__device__ float g_qproj[B_ * D_];
__device__ float g_attn[B_ * H_ * K_];
__device__ float g_ctx_part[NSPLIT * B_ * D_];
__device__ float g_ctx[B_ * D_];
__device__ float g_gpart[GSPLIT * B_ * D_];

// m16n8k16 fp16 MMA, fp32 accum (base PTX, sm_80+; no sm_103a-gated features)
__device__ __forceinline__ void mma_f16(
    float& c0, float& c1, float& c2, float& c3,
    u32 a0, u32 a1, u32 a2, u32 a3, u32 b0, u32 b1)
{
    asm volatile(
        "mma.sync.aligned.m16n8k16.row.col.f32.f16.f16.f32 "
        "{%0,%1,%2,%3}, {%4,%5,%6,%7}, {%8,%9}, {%0,%1,%2,%3};"
        : "+f"(c0), "+f"(c1), "+f"(c2), "+f"(c3)
        : "r"(a0), "r"(a1), "r"(a2), "r"(a3), "r"(b0), "r"(b1));
}

__device__ __forceinline__ u32 smem_u32(const void* p) {
    u32 a;
    asm("{ .reg .u64 t; cvta.to.shared.u64 t, %1; cvt.u32.u64 %0, t; }" : "=r"(a) : "l"(p));
    return a;
}
__device__ __forceinline__ void cp_async16(u32 dst, const void* src) {
    asm volatile("cp.async.ca.shared.global [%0], [%1], 16;" :: "r"(dst), "l"(src));
}
#define CP_COMMIT() asm volatile("cp.async.commit_group;" ::: "memory")
#define CP_WAIT1()  asm volatile("cp.async.wait_group 1;" ::: "memory")

// Composite key: (monotone(float) << 32) | (0xFFFFFFFF - index)
// Descending composite order == (value desc, index asc) == jax.lax.top_k order.
__device__ __forceinline__ u64 make_ck(float f, int i) {
    u32 x = __float_as_uint(f);
    u32 t = (x & 0x80000000u) ? ~x : (x | 0x80000000u);
    return ((u64)t << 32) | (u32)(0xFFFFFFFFu - (u32)i);
}

// ---------------- selection ----------------
__global__ void k_zero16() {
    int stride = gridDim.x * blockDim.x;
    int gtid = blockIdx.x * blockDim.x + threadIdx.x;
    for (int i = gtid; i < 65536; i += stride)
        g_hist16[i] = 0;
    if (gtid < 1024) g_strip[gtid] = 0;
    if (gtid == 0) { g_num_cand = 0; g_sel_count = 0; }
}

__global__ void k_hist16(const float* __restrict__ prio) {
    int stride = gridDim.x * blockDim.x;
    for (int i = blockIdx.x * blockDim.x + threadIdx.x; i < N_; i += stride) {
        u64 ck = make_ck(prio[i], i);
        u32 bin = (u32)(ck >> 48);
        atomicAdd(&g_hist16[bin], 1u);
        atomicAdd(&g_strip[bin >> 6], 1u);
    }
}

// Single CTA, 1024 threads: find the 16-bit threshold bin. Fully parallel:
// strip histogram (precomputed) + Hillis-Steele scan + parallel boundary pick.
__global__ void k_findbin() {
    __shared__ u32 strip[1024];
    __shared__ u32 arr[64];
    __shared__ int s_st;
    __shared__ u32 s_cum;
    int t = threadIdx.x;

    // strip[t] (descending order) = coarse bin (1023 - t)
    strip[t] = g_strip[1023 - t];
    __syncthreads();

    // inclusive prefix sum over strips (index order = descending bins)
    for (int off = 1; off < 1024; off <<= 1) {
        u32 v = strip[t];
        u32 a = (t >= off) ? strip[t - off] : 0u;
        __syncthreads();
        strip[t] = v + a;
        __syncthreads();
    }

    // boundary strip: first t with prefix >= K
    {
        u32 inc  = strip[t];
        u32 prev = (t == 0) ? 0u : strip[t - 1];
        if (inc >= (u32)K_ && prev < (u32)K_) { s_st = t; s_cum = prev; }
    }
    __syncthreads();

    int st = s_st;
    u32 cum = s_cum;
    // refine within strip: arr[i] = bin (65535 - 64*st - i), descending
    if (t < 64) arr[t] = g_hist16[65535 - 64 * st - t];
    __syncthreads();
    for (int off = 1; off < 64; off <<= 1) {
        u32 v = (t < 64) ? arr[t] : 0u;
        u32 a = (t < 64 && t >= off) ? arr[t - off] : 0u;
        __syncthreads();
        if (t < 64) arr[t] = v + a;
        __syncthreads();
    }
    if (t < 64) {
        u32 R    = (u32)K_ - cum;
        u32 inc  = arr[t];
        u32 prev = (t == 0) ? 0u : arr[t - 1];
        if (inc >= R && prev < R) {
            g_T16 = 65535 - 64 * st - t;
            g_cumAbove = (int)(cum + prev);
        }
    }
}

__global__ void k_compact16(const float* __restrict__ prio) {
    int T16 = g_T16;
    int stride = gridDim.x * blockDim.x;
    for (int i = blockIdx.x * blockDim.x + threadIdx.x; i < N_; i += stride) {
        u64 ck = make_ck(prio[i], i);
        int k16 = (int)(u32)(ck >> 48);
        if (k16 > T16) {
            int p = atomicAdd(&g_sel_count, 1);
            g_sel_ck[p] = ck;
        } else if (k16 == T16) {
            int p = atomicAdd(&g_num_cand, 1);
            g_cand[p] = ck;
        }
    }
}

// Single CTA: refine the low 48 bits among the (tiny) candidate set.
__global__ void k_selfin48() {
    __shared__ u64 sc[4096];
    __shared__ u32 hist[256];
    __shared__ u64 s_pref;
    __shared__ int s_R;
    int t = threadIdx.x;  // 256
    int nc = g_num_cand;
    bool inSm = (nc <= 4096);
    if (inSm) for (int i = t; i < nc; i += 256) sc[i] = g_cand[i];
    if (t == 0) {
        s_pref = ((u64)(u32)g_T16) << 48;
        s_R = K_ - g_cumAbove;
    }
    __syncthreads();
    for (int shift = 40; shift >= 0; shift -= 8) {
        hist[t] = 0;
        __syncthreads();
        u64 pref  = s_pref;
        u64 hmask = (~0ULL) << (shift + 8);
        for (int i = t; i < nc; i += 256) {
            u64 ck = inSm ? sc[i] : g_cand[i];
            if ((ck & hmask) == pref)
                atomicAdd(&hist[(u32)(ck >> shift) & 0xFFu], 1u);
        }
        __syncthreads();
        if (t == 0) {
            int R = s_R, cum = 0, b = 0;
            for (int bb = 255; bb >= 0; bb--) {
                if (cum + (int)hist[bb] >= R) { b = bb; break; }
                cum += (int)hist[bb];
            }
            s_pref = pref | (((u64)(u32)b) << shift);
            s_R = R - cum;
        }
        __syncthreads();
    }
    u64 T = s_pref;
    for (int i = t; i < nc; i += 256) {
        u64 ck = inSm ? sc[i] : g_cand[i];
        if (ck >= T) {
            int p = atomicAdd(&g_sel_count, 1);
            g_sel_ck[p] = ck;
        }
    }
}

// Rank sort: one warp per selected element, pairwise count of larger keys.
__global__ void k_rank() {
    __shared__ u64 s_ck[K_];  // 32 KB
    int t = threadIdx.x;
    for (int i = t; i < K_; i += blockDim.x) s_ck[i] = g_sel_ck[i];
    __syncthreads();
    int warp = t >> 5, lane = t & 31;
    int i = blockIdx.x * 8 + warp;
    u64 my = s_ck[i];
    int cnt = 0;
    for (int j = lane; j < K_; j += 32)
        cnt += (s_ck[j] > my) ? 1 : 0;
#pragma unroll
    for (int o = 16; o > 0; o >>= 1) cnt += __shfl_down_sync(0xFFFFFFFFu, cnt, o);
    if (lane == 0)
        g_sorted_idx[cnt] = (int)(0xFFFFFFFFu - (u32)(my & 0xFFFFFFFFull));
}

// ---------------- pre-convert W: fp16 transpose WT[n][k] ----------------
__global__ void k_cvtW(const float* __restrict__ Wk, const float* __restrict__ Wv) {
    __shared__ float tile[32][33];
    const float* W = blockIdx.z ? Wv : Wk;
    __half* WT     = blockIdx.z ? g_WvH : g_WkH;
    int n  = blockIdx.x * 32 + threadIdx.x;
    int k0 = blockIdx.y * 32;
    for (int i = threadIdx.y; i < 32; i += 8)
        tile[i][threadIdx.x] = W[(size_t)(k0 + i) * D_ + n];
    __syncthreads();
    int k   = k0 + threadIdx.x;
    int nn0 = blockIdx.x * 32;
    for (int i = threadIdx.y; i < 32; i += 8)
        WT[(size_t)(nn0 + i) * D_ + k] = __float2half_rn(tile[threadIdx.x][i]);
}

// ---------------- pre-gather A rows as fp16 ----------------
__global__ void k_gatherA(const float* __restrict__ buffer) {
    int row = blockIdx.x;                 // 4096
    const float4* src = (const float4*)(buffer + (size_t)g_sorted_idx[row] * D_);
    uint2* dst = (uint2*)(g_aH + (size_t)row * D_);
    int t = threadIdx.x;                  // 256
    float4 v = src[t];
    __half2 h0 = __floats2half2_rn(v.x, v.y);
    __half2 h1 = __floats2half2_rn(v.z, v.w);
    dst[t] = make_uint2(*(u32*)&h0, *(u32*)&h1);
}

// ============ K/V projection: fp16 m16n8k16 + cp.async 3-stage pipeline ======
// (Round-9 verified version: manual LDS fragment loads.)
// CTA tile 128x128, 8 warps, warp tile 64x32 (4x4 frags of 16x8), K chunks of 16.
// Stage layout (u32 words): As[128][12] then Bs[128][12]; stride 12 -> frag
// loads conflict-free (12*grp+qid mod 32 all distinct).
#define KV_CH 16
#define KV_NCH (D_ / KV_CH)        // 64
#define KV_STAGE_U32 (2 * 128 * 12)  // 3072 u32 = 12288 B
#define KV_SMEM_BYTES (3 * KV_STAGE_U32 * 4)   // 36864

__global__ void __launch_bounds__(256, 2)
k_kvproj_mma(const float* __restrict__ bk, const float* __restrict__ bv)
{
    extern __shared__ u32 dsm[];
    u32 sbase = smem_u32(dsm);

    int z  = blockIdx.z;
    const __half* WH  = z ? g_WvH : g_WkH;
    const float* bias = z ? bv : bk;
    float* out        = z ? g_vproj : g_kproj;
    int m0 = blockIdx.y * 128;
    int n0 = blockIdx.x * 128;

    int t    = threadIdx.x;
    int lane = t & 31, wid = t >> 5;
    int grp  = lane >> 2, qid = lane & 3;
    int wm   = (wid >> 2) * 64;   // 0 / 64
    int wn   = (wid & 3) * 32;    // 0 / 32 / 64 / 96

    // staging: thread t -> row = t>>1 (A-row m / B-row n), seg = t&1 (16B half)
    int row = t >> 1, seg = t & 1;
    const char* aSrc = (const char*)(g_aH + (size_t)(m0 + row) * D_) + seg * 16;
    const char* bSrc = (const char*)(WH   + (size_t)(n0 + row) * D_) + seg * 16;
    u32 dstA = sbase + (u32)(row * 48 + seg * 16);          // within-stage offsets
    u32 dstB = dstA + 128 * 48;

#define KV_ISSUE(c) do { \
    u32 _so = (u32)(((c) % 3) * (KV_STAGE_U32 * 4)); \
    cp_async16(dstA + _so, aSrc + (size_t)(c) * 32); \
    cp_async16(dstB + _so, bSrc + (size_t)(c) * 32); \
    CP_COMMIT(); \
} while (0)

    float acc[4][4][4];
#pragma unroll
    for (int i = 0; i < 4; i++)
#pragma unroll
        for (int j = 0; j < 4; j++)
#pragma unroll
            for (int q = 0; q < 4; q++) acc[i][j][q] = 0.0f;

    KV_ISSUE(0);
    KV_ISSUE(1);

    for (int c = 0; c < KV_NCH; c++) {
        CP_WAIT1();
        __syncthreads();
        if (c + 2 < KV_NCH) KV_ISSUE(c + 2);

        const u32* As = dsm + (c % 3) * KV_STAGE_U32;
        const u32* Bs = As + 128 * 12;
        u32 af[4][4], bf[4][2];
#pragma unroll
        for (int mf = 0; mf < 4; mf++) {
            int r = wm + mf * 16 + grp;
            af[mf][0] = As[r * 12 + qid];
            af[mf][1] = As[(r + 8) * 12 + qid];
            af[mf][2] = As[r * 12 + qid + 4];
            af[mf][3] = As[(r + 8) * 12 + qid + 4];
        }
#pragma unroll
        for (int nf = 0; nf < 4; nf++) {
            int n = wn + nf * 8 + grp;
            bf[nf][0] = Bs[n * 12 + qid];
            bf[nf][1] = Bs[n * 12 + qid + 4];
        }
#pragma unroll
        for (int mf = 0; mf < 4; mf++)
#pragma unroll
            for (int nf = 0; nf < 4; nf++)
                mma_f16(acc[mf][nf][0], acc[mf][nf][1], acc[mf][nf][2], acc[mf][nf][3],
                        af[mf][0], af[mf][1], af[mf][2], af[mf][3],
                        bf[nf][0], bf[nf][1]);
    }

    // epilogue: D[m][n] + bias[n]
#pragma unroll
    for (int mf = 0; mf < 4; mf++) {
#pragma unroll
        for (int nf = 0; nf < 4; nf++) {
            int n = n0 + wn + nf * 8 + 2 * qid;
            float bv0 = bias[n], bv1 = bias[n + 1];
            int r0 = m0 + wm + mf * 16 + grp;
            float2 v0 = make_float2(acc[mf][nf][0] + bv0, acc[mf][nf][1] + bv1);
            float2 v1 = make_float2(acc[mf][nf][2] + bv0, acc[mf][nf][3] + bv1);
            *(float2*)(out + (size_t)r0 * D_ + n)       = v0;
            *(float2*)(out + (size_t)(r0 + 8) * D_ + n) = v1;
        }
    }
#undef KV_ISSUE
}

// ---------------- M=32 GEMM, split-K (q proj: mode 0, out proj: mode 1) -----
__global__ void k_gemm32s(const float* __restrict__ Aext,
                          const float* __restrict__ W, int mode)
{
    const float* A = (mode == 0) ? Aext : g_ctx;
    int n0 = blockIdx.x * 128;
    int ks = blockIdx.y * (D_ / GSPLIT);   // 256-wide K slice

    __shared__ float As[32][36];   // [k][b]
    __shared__ float Bs[32][128];  // [k][n]
    int t = threadIdx.x;
    float acc[4][4] = {};
    int rm = (t >> 5) * 4, rn = (t & 31) * 4;
    int ab = t >> 3, akq = (t & 7) * 4;

    for (int k0 = ks; k0 < ks + D_ / GSPLIT; k0 += 32) {
        float4 av = *(const float4*)(A + (size_t)ab * D_ + k0 + akq);
        As[akq+0][ab]=av.x; As[akq+1][ab]=av.y; As[akq+2][ab]=av.z; As[akq+3][ab]=av.w;
#pragma unroll
        for (int p = 0; p < 4; p++) {
            int id = t + p * 256;
            int br = id >> 5, bc = (id & 31) * 4;
            *(float4*)&Bs[br][bc] = *(const float4*)(W + (size_t)(k0 + br) * D_ + n0 + bc);
        }
        __syncthreads();
#pragma unroll
        for (int kk = 0; kk < 32; kk++) {
            float a[4], b[4];
            *(float4*)&a[0] = *(const float4*)&As[kk][rm];
            *(float4*)&b[0] = *(const float4*)&Bs[kk][rn];
#pragma unroll
            for (int i = 0; i < 4; i++)
#pragma unroll
                for (int j = 0; j < 4; j++)
                    acc[i][j] += a[i] * b[j];
        }
        __syncthreads();
    }
#pragma unroll
    for (int i = 0; i < 4; i++) {
        float* op = g_gpart + ((size_t)blockIdx.y * B_ + rm + i) * D_ + n0 + rn;
#pragma unroll
        for (int j = 0; j < 4; j++)
            op[j] = acc[i][j];
    }
}

__global__ void k_gemmred(const float* __restrict__ bias,
                          float* __restrict__ outext, int mode)
{
    float* dst = (mode == 0) ? g_qproj : outext;
    int i = blockIdx.x * blockDim.x + threadIdx.x;  // 32768
    int n = i & (D_ - 1);
    float s = bias[n];
#pragma unroll
    for (int sp = 0; sp < GSPLIT; sp++) s += g_gpart[(size_t)sp * B_ * D_ + i];
    dst[i] = s;
}

// ---------------- scores[b,h,j] = scale * q[b,h,:] . k[j,h,:] ---------------
__global__ void k_scores() {
    int j0 = blockIdx.x * 128;
    int h  = blockIdx.y;
    __shared__ float As[32][36];   // [d][b]
    __shared__ float Bs[32][132];  // [d][j]
    int t = threadIdx.x;
    float acc[4][4] = {};
    int rm = (t >> 5) * 4, rn = (t & 31) * 4;
    int ab = t >> 3, akq = (t & 7) * 4;

    for (int d0 = 0; d0 < HD_; d0 += 32) {
        float4 av = *(const float4*)(g_qproj + (size_t)ab * D_ + h * HD_ + d0 + akq);
        As[akq+0][ab]=av.x; As[akq+1][ab]=av.y; As[akq+2][ab]=av.z; As[akq+3][ab]=av.w;
#pragma unroll
        for (int p = 0; p < 4; p++) {
            int id = t + p * 256;
            int jr = id >> 3, dq = (id & 7) * 4;
            float4 bvv = *(const float4*)(g_kproj + (size_t)(j0 + jr) * D_ + h * HD_ + d0 + dq);
            Bs[dq+0][jr]=bvv.x; Bs[dq+1][jr]=bvv.y; Bs[dq+2][jr]=bvv.z; Bs[dq+3][jr]=bvv.w;
        }
        __syncthreads();
#pragma unroll
        for (int kk = 0; kk < 32; kk++) {
            float a[4], b[4];
            *(float4*)&a[0] = *(const float4*)&As[kk][rm];
            *(float4*)&b[0] = *(const float4*)&Bs[kk][rn];
#pragma unroll
            for (int i = 0; i < 4; i++)
#pragma unroll
                for (int j = 0; j < 4; j++)
                    acc[i][j] += a[i] * b[j];
        }
        __syncthreads();
    }
    const float scale = 0.08838834764831845f;  // 128^-0.5
#pragma unroll
    for (int i = 0; i < 4; i++)
#pragma unroll
        for (int j = 0; j < 4; j++)
            g_attn[((size_t)(rm + i) * H_ + h) * K_ + j0 + rn + j] = acc[i][j] * scale;
}

// ---------------- softmax over j (in place), one CTA per (b,h) row ----------
__global__ void k_softmax() {
    int row = blockIdx.x;
    float* p = g_attn + (size_t)row * K_;
    __shared__ float sd[K_];
    __shared__ float red[256];
    int t = threadIdx.x;
    float mx = -1e30f;
    for (int i = t; i < K_; i += 256) { float v = p[i]; sd[i] = v; mx = fmaxf(mx, v); }
    red[t] = mx; __syncthreads();
    for (int o = 128; o > 0; o >>= 1) { if (t < o) red[t] = fmaxf(red[t], red[t + o]); __syncthreads(); }
    mx = red[0]; __syncthreads();
    float sum = 0.0f;
    for (int i = t; i < K_; i += 256) { float e = expf(sd[i] - mx); sd[i] = e; sum += e; }
    red[t] = sum; __syncthreads();
    for (int o = 128; o > 0; o >>= 1) { if (t < o) red[t] += red[t + o]; __syncthreads(); }
    float inv = 1.0f / red[0];
    for (int i = t; i < K_; i += 256) p[i] = sd[i] * inv;
}

// ---------------- attn_avg = mean over heads -> d_out[32768:] ---------------
__global__ void k_avg(float* __restrict__ out2) {
    int idx = blockIdx.x * blockDim.x + threadIdx.x;  // 131072 total
    int b = idx >> 12, j = idx & 4095;
    float s = 0.0f;
#pragma unroll
    for (int h = 0; h < H_; h++) s += g_attn[((size_t)b * H_ + h) * K_ + j];
    out2[(size_t)b * K_ + j] = s * 0.125f;
}

// ---------------- ctx partials: attn[b,h,:] @ v[:,h,:] over j-split ---------
__global__ void k_ctxpart() {
    int h  = blockIdx.x;       // 8
    int sp = blockIdx.y;       // 16
    int jbase = sp * (K_ / NSPLIT);   // 256 j per split
    __shared__ float As[32][36];    // [j][b]
    __shared__ float Bs[32][128];   // [j][d]
    int t = threadIdx.x;
    float acc[4][4] = {};
    int rm = (t >> 5) * 4, rn = (t & 31) * 4;
    int ab = t >> 3, ajq = (t & 7) * 4;

    for (int k0 = 0; k0 < K_ / NSPLIT; k0 += 32) {
        float4 av = *(const float4*)(g_attn + ((size_t)ab * H_ + h) * K_ + jbase + k0 + ajq);
        As[ajq+0][ab]=av.x; As[ajq+1][ab]=av.y; As[ajq+2][ab]=av.z; As[ajq+3][ab]=av.w;
#pragma unroll
        for (int p = 0; p < 4; p++) {
            int id = t + p * 256;
            int jr = id >> 5, dc = (id & 31) * 4;
            *(float4*)&Bs[jr][dc] =
                *(const float4*)(g_vproj + (size_t)(jbase + k0 + jr) * D_ + h * HD_ + dc);
        }
        __syncthreads();
#pragma unroll
        for (int kk = 0; kk < 32; kk++) {
            float a[4], b[4];
            *(float4*)&a[0] = *(const float4*)&As[kk][rm];
            *(float4*)&b[0] = *(const float4*)&Bs[kk][rn];
#pragma unroll
            for (int i = 0; i < 4; i++)
#pragma unroll
                for (int j = 0; j < 4; j++)
                    acc[i][j] += a[i] * b[j];
        }
        __syncthreads();
    }
#pragma unroll
    for (int i = 0; i < 4; i++)
#pragma unroll
        for (int j = 0; j < 4; j++)
            g_ctx_part[((size_t)sp * B_ + rm + i) * D_ + h * HD_ + rn + j] = acc[i][j];
}

__global__ void k_ctxred() {
    int i = blockIdx.x * blockDim.x + threadIdx.x;  // 32768
    float s = 0.0f;
#pragma unroll
    for (int sp = 0; sp < NSPLIT; sp++) s += g_ctx_part[(size_t)sp * B_ * D_ + i];
    g_ctx[i] = s;
}

// ---------------- launch ----------------
extern "C" void kernel_launch(void* const* d_in, const int* in_sizes, int n_in,
                              void* d_out, int out_size) {
    const float* query  = (const float*)d_in[0];
    const float* buffer = (const float*)d_in[1];
    const float* prio   = (const float*)d_in[2];
    const float* Wq     = (const float*)d_in[3];
    const float* bq     = (const float*)d_in[4];
    const float* Wk     = (const float*)d_in[5];
    const float* bk     = (const float*)d_in[6];
    const float* Wv     = (const float*)d_in[7];
    const float* bv     = (const float*)d_in[8];
    const float* Wo     = (const float*)d_in[9];
    const float* bo     = (const float*)d_in[10];
    float* out = (float*)d_out;   // [0,32768): retrieved, [32768,163840): attn_avg

    // selection + weight pre-convert (cvtW independent of selection)
    k_zero16<<<64, 256>>>();
    k_hist16<<<64, 256>>>(prio);
    k_cvtW<<<dim3(32, 32, 2), dim3(32, 8)>>>(Wk, Wv);
    k_findbin<<<1, 1024>>>();
    k_compact16<<<64, 256>>>(prio);
    k_selfin48<<<1, 256>>>();
    k_rank<<<K_ / 8, 256>>>();
    k_gatherA<<<K_, 256>>>(buffer);

    // K/V projection on tensor cores (fp16 mma, cp.async 3-stage pipeline)
    k_kvproj_mma<<<dim3(8, 32, 2), 256, KV_SMEM_BYTES>>>(bk, bv);

    // attention tail (q projection via split-K)
    k_gemm32s<<<dim3(8, GSPLIT), 256>>>(query, Wq, 0);
    k_gemmred<<<128, 256>>>(bq, nullptr, 0);
    k_scores<<<dim3(32, 8), 256>>>();
    k_softmax<<<256, 256>>>();
    k_avg<<<512, 256>>>(out + B_ * D_);
    k_ctxpart<<<dim3(8, NSPLIT), 256>>>();
    k_ctxred<<<128, 256>>>();
    k_gemm32s<<<dim3(8, GSPLIT), 256>>>(nullptr, Wo, 1);   // output projection
    k_gemmred<<<128, 256>>>(bo, out, 1);
}

// round 12
// speedup vs baseline: 1.5107x; 1.0072x over previous
#include <cuda_runtime.h>
#include <cuda_fp16.h>
#include <math.h>
#include <stdint.h>

// Problem constants (fixed by the dataset)
#define B_   32
#define D_   1024
#define N_   65536
#define K_   4096
#define H_   8
#define HD_  128
#define NSPLIT 16
#define GSPLIT 4

typedef unsigned long long u64;
typedef unsigned int       u32;

// ---------------- scratch (static device globals; no allocation) -------------
__device__ u32  g_hist16[65536];
__device__ u32  g_strip[1024];      // coarse histogram: bin >> 6
__device__ int  g_T16;
__device__ int  g_cumAbove;
__device__ int  g_num_cand;
__device__ int  g_sel_count;
__device__ u64  g_cand[N_];
__device__ u64  g_sel_ck[K_];
__device__ int  g_sorted_idx[K_];
__device__ __half g_WkH[D_ * D_];   // W^T as fp16: [n][k]
__device__ __half g_WvH[D_ * D_];
__device__ __half g_aH[K_ * D_];    // gathered rows as fp16: [m][k]
__device__ float g_kproj[K_ * D_];
__device__ float g_vproj[K_ * D_];
__device__ float g_qproj[B_ * D_];
__device__ float g_attn[B_ * H_ * K_];
__device__ float g_ctx_part[NSPLIT * B_ * D_];
__device__ float g_ctx[B_ * D_];
__device__ float g_gpart[GSPLIT * B_ * D_];

// m16n8k16 fp16 MMA, fp32 accum (base PTX, sm_80+; no sm_103a-gated features)
__device__ __forceinline__ void mma_f16(
    float& c0, float& c1, float& c2, float& c3,
    u32 a0, u32 a1, u32 a2, u32 a3, u32 b0, u32 b1)
{
    asm volatile(
        "mma.sync.aligned.m16n8k16.row.col.f32.f16.f16.f32 "
        "{%0,%1,%2,%3}, {%4,%5,%6,%7}, {%8,%9}, {%0,%1,%2,%3};"
        : "+f"(c0), "+f"(c1), "+f"(c2), "+f"(c3)
        : "r"(a0), "r"(a1), "r"(a2), "r"(a3), "r"(b0), "r"(b1));
}

__device__ __forceinline__ u32 smem_u32(const void* p) {
    u32 a;
    asm("{ .reg .u64 t; cvta.to.shared.u64 t, %1; cvt.u32.u64 %0, t; }" : "=r"(a) : "l"(p));
    return a;
}
__device__ __forceinline__ void cp_async16(u32 dst, const void* src) {
    asm volatile("cp.async.ca.shared.global [%0], [%1], 16;" :: "r"(dst), "l"(src));
}
#define CP_COMMIT() asm volatile("cp.async.commit_group;" ::: "memory")
#define CP_WAIT1()  asm volatile("cp.async.wait_group 1;" ::: "memory")

// Composite key: (monotone(float) << 32) | (0xFFFFFFFF - index)
// Descending composite order == (value desc, index asc) == jax.lax.top_k order.
__device__ __forceinline__ u64 make_ck(float f, int i) {
    u32 x = __float_as_uint(f);
    u32 t = (x & 0x80000000u) ? ~x : (x | 0x80000000u);
    return ((u64)t << 32) | (u32)(0xFFFFFFFFu - (u32)i);
}

// ---------------- selection ----------------
__global__ void k_zero16() {
    int stride = gridDim.x * blockDim.x;
    int gtid = blockIdx.x * blockDim.x + threadIdx.x;
    for (int i = gtid; i < 65536; i += stride)
        g_hist16[i] = 0;
    if (gtid < 1024) g_strip[gtid] = 0;
    if (gtid == 0) { g_num_cand = 0; g_sel_count = 0; }
}

__global__ void k_hist16(const float* __restrict__ prio) {
    int stride = gridDim.x * blockDim.x;
    for (int i = blockIdx.x * blockDim.x + threadIdx.x; i < N_; i += stride) {
        u64 ck = make_ck(prio[i], i);
        u32 bin = (u32)(ck >> 48);
        atomicAdd(&g_hist16[bin], 1u);
        atomicAdd(&g_strip[bin >> 6], 1u);
    }
}

// Single CTA, 1024 threads: find the 16-bit threshold bin. Fully parallel:
// strip histogram (precomputed) + Hillis-Steele scan + parallel boundary pick.
__global__ void k_findbin() {
    __shared__ u32 strip[1024];
    __shared__ u32 arr[64];
    __shared__ int s_st;
    __shared__ u32 s_cum;
    int t = threadIdx.x;

    // strip[t] (descending order) = coarse bin (1023 - t)
    strip[t] = g_strip[1023 - t];
    __syncthreads();

    // inclusive prefix sum over strips (index order = descending bins)
    for (int off = 1; off < 1024; off <<= 1) {
        u32 v = strip[t];
        u32 a = (t >= off) ? strip[t - off] : 0u;
        __syncthreads();
        strip[t] = v + a;
        __syncthreads();
    }

    // boundary strip: first t with prefix >= K
    {
        u32 inc  = strip[t];
        u32 prev = (t == 0) ? 0u : strip[t - 1];
        if (inc >= (u32)K_ && prev < (u32)K_) { s_st = t; s_cum = prev; }
    }
    __syncthreads();

    int st = s_st;
    u32 cum = s_cum;
    // refine within strip: arr[i] = bin (65535 - 64*st - i), descending
    if (t < 64) arr[t] = g_hist16[65535 - 64 * st - t];
    __syncthreads();
    for (int off = 1; off < 64; off <<= 1) {
        u32 v = (t < 64) ? arr[t] : 0u;
        u32 a = (t < 64 && t >= off) ? arr[t - off] : 0u;
        __syncthreads();
        if (t < 64) arr[t] = v + a;
        __syncthreads();
    }
    if (t < 64) {
        u32 R    = (u32)K_ - cum;
        u32 inc  = arr[t];
        u32 prev = (t == 0) ? 0u : arr[t - 1];
        if (inc >= R && prev < R) {
            g_T16 = 65535 - 64 * st - t;
            g_cumAbove = (int)(cum + prev);
        }
    }
}

__global__ void k_compact16(const float* __restrict__ prio) {
    int T16 = g_T16;
    int stride = gridDim.x * blockDim.x;
    for (int i = blockIdx.x * blockDim.x + threadIdx.x; i < N_; i += stride) {
        u64 ck = make_ck(prio[i], i);
        int k16 = (int)(u32)(ck >> 48);
        if (k16 > T16) {
            int p = atomicAdd(&g_sel_count, 1);
            g_sel_ck[p] = ck;
        } else if (k16 == T16) {
            int p = atomicAdd(&g_num_cand, 1);
            g_cand[p] = ck;
        }
    }
}

// Single CTA: refine the low 48 bits among the (tiny) candidate set.
__global__ void k_selfin48() {
    __shared__ u64 sc[4096];
    __shared__ u32 hist[256];
    __shared__ u64 s_pref;
    __shared__ int s_R;
    int t = threadIdx.x;  // 256
    int nc = g_num_cand;
    bool inSm = (nc <= 4096);
    if (inSm) for (int i = t; i < nc; i += 256) sc[i] = g_cand[i];
    if (t == 0) {
        s_pref = ((u64)(u32)g_T16) << 48;
        s_R = K_ - g_cumAbove;
    }
    __syncthreads();
    for (int shift = 40; shift >= 0; shift -= 8) {
        hist[t] = 0;
        __syncthreads();
        u64 pref  = s_pref;
        u64 hmask = (~0ULL) << (shift + 8);
        for (int i = t; i < nc; i += 256) {
            u64 ck = inSm ? sc[i] : g_cand[i];
            if ((ck & hmask) == pref)
                atomicAdd(&hist[(u32)(ck >> shift) & 0xFFu], 1u);
        }
        __syncthreads();
        if (t == 0) {
            int R = s_R, cum = 0, b = 0;
            for (int bb = 255; bb >= 0; bb--) {
                if (cum + (int)hist[bb] >= R) { b = bb; break; }
                cum += (int)hist[bb];
            }
            s_pref = pref | (((u64)(u32)b) << shift);
            s_R = R - cum;
        }
        __syncthreads();
    }
    u64 T = s_pref;
    for (int i = t; i < nc; i += 256) {
        u64 ck = inSm ? sc[i] : g_cand[i];
        if (ck >= T) {
            int p = atomicAdd(&g_sel_count, 1);
            g_sel_ck[p] = ck;
        }
    }
}

// Rank sort: one warp per selected element, pairwise count of larger keys.
__global__ void k_rank() {
    __shared__ u64 s_ck[K_];  // 32 KB
    int t = threadIdx.x;
    for (int i = t; i < K_; i += blockDim.x) s_ck[i] = g_sel_ck[i];
    __syncthreads();
    int warp = t >> 5, lane = t & 31;
    int i = blockIdx.x * 8 + warp;
    u64 my = s_ck[i];
    int cnt = 0;
    for (int j = lane; j < K_; j += 32)
        cnt += (s_ck[j] > my) ? 1 : 0;
#pragma unroll
    for (int o = 16; o > 0; o >>= 1) cnt += __shfl_down_sync(0xFFFFFFFFu, cnt, o);
    if (lane == 0)
        g_sorted_idx[cnt] = (int)(0xFFFFFFFFu - (u32)(my & 0xFFFFFFFFull));
}

// ---------------- pre-convert W: fp16 transpose WT[n][k] ----------------
__global__ void k_cvtW(const float* __restrict__ Wk, const float* __restrict__ Wv) {
    __shared__ float tile[32][33];
    const float* W = blockIdx.z ? Wv : Wk;
    __half* WT     = blockIdx.z ? g_WvH : g_WkH;
    int n  = blockIdx.x * 32 + threadIdx.x;
    int k0 = blockIdx.y * 32;
    for (int i = threadIdx.y; i < 32; i += 8)
        tile[i][threadIdx.x] = W[(size_t)(k0 + i) * D_ + n];
    __syncthreads();
    int k   = k0 + threadIdx.x;
    int nn0 = blockIdx.x * 32;
    for (int i = threadIdx.y; i < 32; i += 8)
        WT[(size_t)(nn0 + i) * D_ + k] = __float2half_rn(tile[threadIdx.x][i]);
}

// ---------------- pre-gather A rows as fp16 ----------------
__global__ void k_gatherA(const float* __restrict__ buffer) {
    int row = blockIdx.x;                 // 4096
    const float4* src = (const float4*)(buffer + (size_t)g_sorted_idx[row] * D_);
    uint2* dst = (uint2*)(g_aH + (size_t)row * D_);
    int t = threadIdx.x;                  // 256
    float4 v = src[t];
    __half2 h0 = __floats2half2_rn(v.x, v.y);
    __half2 h1 = __floats2half2_rn(v.z, v.w);
    dst[t] = make_uint2(*(u32*)&h0, *(u32*)&h1);
}

// ============ K/V projection: fp16 m16n8k16 + cp.async 3-stage pipeline ======
// CTA tile 128x128, 8 warps, warp tile 64x32 (4x4 frags of 16x8), K chunks of 32
// (two k-steps of 16 per barrier). Stage layout (u32 words): As[128][28] then
// Bs[128][28]; stride 28 -> frag loads conflict-free
// (28*grp mod 32 = {0,28,24,20,16,12,8,4}, +qid(0..3) all distinct).
#define KV_CH 32
#define KV_NCH (D_ / KV_CH)            // 32
#define KV_ROW_U32 28
#define KV_STAGE_U32 (2 * 128 * KV_ROW_U32)  // 7168 u32 = 28672 B
#define KV_STAGE_B   (KV_STAGE_U32 * 4)
#define KV_SMEM_BYTES (3 * KV_STAGE_B)       // 86016

__global__ void __launch_bounds__(256, 2)
k_kvproj_mma(const float* __restrict__ bk, const float* __restrict__ bv)
{
    extern __shared__ u32 dsm[];
    u32 sbase = smem_u32(dsm);

    int z  = blockIdx.z;
    const __half* WH  = z ? g_WvH : g_WkH;
    const float* bias = z ? bv : bk;
    float* out        = z ? g_vproj : g_kproj;
    int m0 = blockIdx.y * 128;
    int n0 = blockIdx.x * 128;

    int t    = threadIdx.x;
    int lane = t & 31, wid = t >> 5;
    int grp  = lane >> 2, qid = lane & 3;
    int wm   = (wid >> 2) * 64;   // 0 / 64
    int wn   = (wid & 3) * 32;    // 0 / 32 / 64 / 96

    // staging: thread t -> row = t>>1, half = (t&1)*32 bytes (2x16B segments)
    // per chunk a row holds 32 fp16 = 64 B, padded to 112 B (28 u32).
    int row = t >> 1, hf = (t & 1) * 32;
    const char* aSrc = (const char*)(g_aH + (size_t)(m0 + row) * D_) + hf;
    const char* bSrc = (const char*)(WH   + (size_t)(n0 + row) * D_) + hf;
    u32 dstA = sbase + (u32)(row * 112 + hf);                 // within-stage
    u32 dstB = dstA + (u32)(128 * 112);

#define KV_ISSUE(c) do { \
    u32 _so = (u32)(((c) % 3) * KV_STAGE_B); \
    const char* _as = aSrc + (size_t)(c) * 64; \
    const char* _bs = bSrc + (size_t)(c) * 64; \
    cp_async16(dstA + _so,      _as); \
    cp_async16(dstA + _so + 16, _as + 16); \
    cp_async16(dstB + _so,      _bs); \
    cp_async16(dstB + _so + 16, _bs + 16); \
    CP_COMMIT(); \
} while (0)

    float acc[4][4][4];
#pragma unroll
    for (int i = 0; i < 4; i++)
#pragma unroll
        for (int j = 0; j < 4; j++)
#pragma unroll
            for (int q = 0; q < 4; q++) acc[i][j][q] = 0.0f;

    KV_ISSUE(0);
    KV_ISSUE(1);

    for (int c = 0; c < KV_NCH; c++) {
        CP_WAIT1();
        __syncthreads();
        if (c + 2 < KV_NCH) KV_ISSUE(c + 2);

        const u32* As = dsm + (c % 3) * KV_STAGE_U32;
        const u32* Bs = As + 128 * KV_ROW_U32;
#pragma unroll
        for (int kk = 0; kk < 2; kk++) {
            int kb = kk * 8;
            u32 af[4][4], bf[4][2];
#pragma unroll
            for (int mf = 0; mf < 4; mf++) {
                int r = wm + mf * 16 + grp;
                af[mf][0] = As[r * KV_ROW_U32 + kb + qid];
                af[mf][1] = As[(r + 8) * KV_ROW_U32 + kb + qid];
                af[mf][2] = As[r * KV_ROW_U32 + kb + qid + 4];
                af[mf][3] = As[(r + 8) * KV_ROW_U32 + kb + qid + 4];
            }
#pragma unroll
            for (int nf = 0; nf < 4; nf++) {
                int n = wn + nf * 8 + grp;
                bf[nf][0] = Bs[n * KV_ROW_U32 + kb + qid];
                bf[nf][1] = Bs[n * KV_ROW_U32 + kb + qid + 4];
            }
#pragma unroll
            for (int mf = 0; mf < 4; mf++)
#pragma unroll
                for (int nf = 0; nf < 4; nf++)
                    mma_f16(acc[mf][nf][0], acc[mf][nf][1], acc[mf][nf][2], acc[mf][nf][3],
                            af[mf][0], af[mf][1], af[mf][2], af[mf][3],
                            bf[nf][0], bf[nf][1]);
        }
    }

    // epilogue: D[m][n] + bias[n]
#pragma unroll
    for (int mf = 0; mf < 4; mf++) {
#pragma unroll
        for (int nf = 0; nf < 4; nf++) {
            int n = n0 + wn + nf * 8 + 2 * qid;
            float bv0 = bias[n], bv1 = bias[n + 1];
            int r0 = m0 + wm + mf * 16 + grp;
            float2 v0 = make_float2(acc[mf][nf][0] + bv0, acc[mf][nf][1] + bv1);
            float2 v1 = make_float2(acc[mf][nf][2] + bv0, acc[mf][nf][3] + bv1);
            *(float2*)(out + (size_t)r0 * D_ + n)       = v0;
            *(float2*)(out + (size_t)(r0 + 8) * D_ + n) = v1;
        }
    }
#undef KV_ISSUE
}

// ---------------- M=32 GEMM, split-K (q proj: mode 0, out proj: mode 1) -----
__global__ void k_gemm32s(const float* __restrict__ Aext,
                          const float* __restrict__ W, int mode)
{
    const float* A = (mode == 0) ? Aext : g_ctx;
    int n0 = blockIdx.x * 128;
    int ks = blockIdx.y * (D_ / GSPLIT);   // 256-wide K slice

    __shared__ float As[32][36];   // [k][b]
    __shared__ float Bs[32][128];  // [k][n]
    int t = threadIdx.x;
    float acc[4][4] = {};
    int rm = (t >> 5) * 4, rn = (t & 31) * 4;
    int ab = t >> 3, akq = (t & 7) * 4;

    for (int k0 = ks; k0 < ks + D_ / GSPLIT; k0 += 32) {
        float4 av = *(const float4*)(A + (size_t)ab * D_ + k0 + akq);
        As[akq+0][ab]=av.x; As[akq+1][ab]=av.y; As[akq+2][ab]=av.z; As[akq+3][ab]=av.w;
#pragma unroll
        for (int p = 0; p < 4; p++) {
            int id = t + p * 256;
            int br = id >> 5, bc = (id & 31) * 4;
            *(float4*)&Bs[br][bc] = *(const float4*)(W + (size_t)(k0 + br) * D_ + n0 + bc);
        }
        __syncthreads();
#pragma unroll
        for (int kk = 0; kk < 32; kk++) {
            float a[4], b[4];
            *(float4*)&a[0] = *(const float4*)&As[kk][rm];
            *(float4*)&b[0] = *(const float4*)&Bs[kk][rn];
#pragma unroll
            for (int i = 0; i < 4; i++)
#pragma unroll
                for (int j = 0; j < 4; j++)
                    acc[i][j] += a[i] * b[j];
        }
        __syncthreads();
    }
#pragma unroll
    for (int i = 0; i < 4; i++) {
        float* op = g_gpart + ((size_t)blockIdx.y * B_ + rm + i) * D_ + n0 + rn;
#pragma unroll
        for (int j = 0; j < 4; j++)
            op[j] = acc[i][j];
    }
}

__global__ void k_gemmred(const float* __restrict__ bias,
                          float* __restrict__ outext, int mode)
{
    float* dst = (mode == 0) ? g_qproj : outext;
    int i = blockIdx.x * blockDim.x + threadIdx.x;  // 32768
    int n = i & (D_ - 1);
    float s = bias[n];
#pragma unroll
    for (int sp = 0; sp < GSPLIT; sp++) s += g_gpart[(size_t)sp * B_ * D_ + i];
    dst[i] = s;
}

// ---------------- scores[b,h,j] = scale * q[b,h,:] . k[j,h,:] ---------------
__global__ void k_scores() {
    int j0 = blockIdx.x * 128;
    int h  = blockIdx.y;
    __shared__ float As[32][36];   // [d][b]
    __shared__ float Bs[32][132];  // [d][j]
    int t = threadIdx.x;
    float acc[4][4] = {};
    int rm = (t >> 5) * 4, rn = (t & 31) * 4;
    int ab = t >> 3, akq = (t & 7) * 4;

    for (int d0 = 0; d0 < HD_; d0 += 32) {
        float4 av = *(const float4*)(g_qproj + (size_t)ab * D_ + h * HD_ + d0 + akq);
        As[akq+0][ab]=av.x; As[akq+1][ab]=av.y; As[akq+2][ab]=av.z; As[akq+3][ab]=av.w;
#pragma unroll
        for (int p = 0; p < 4; p++) {
            int id = t + p * 256;
            int jr = id >> 3, dq = (id & 7) * 4;
            float4 bvv = *(const float4*)(g_kproj + (size_t)(j0 + jr) * D_ + h * HD_ + d0 + dq);
            Bs[dq+0][jr]=bvv.x; Bs[dq+1][jr]=bvv.y; Bs[dq+2][jr]=bvv.z; Bs[dq+3][jr]=bvv.w;
        }
        __syncthreads();
#pragma unroll
        for (int kk = 0; kk < 32; kk++) {
            float a[4], b[4];
            *(float4*)&a[0] = *(const float4*)&As[kk][rm];
            *(float4*)&b[0] = *(const float4*)&Bs[kk][rn];
#pragma unroll
            for (int i = 0; i < 4; i++)
#pragma unroll
                for (int j = 0; j < 4; j++)
                    acc[i][j] += a[i] * b[j];
        }
        __syncthreads();
    }
    const float scale = 0.08838834764831845f;  // 128^-0.5
#pragma unroll
    for (int i = 0; i < 4; i++)
#pragma unroll
        for (int j = 0; j < 4; j++)
            g_attn[((size_t)(rm + i) * H_ + h) * K_ + j0 + rn + j] = acc[i][j] * scale;
}

// ---------------- softmax over j (in place), one CTA per (b,h) row ----------
__global__ void k_softmax() {
    int row = blockIdx.x;
    float* p = g_attn + (size_t)row * K_;
    __shared__ float sd[K_];
    __shared__ float red[256];
    int t = threadIdx.x;
    float mx = -1e30f;
    for (int i = t; i < K_; i += 256) { float v = p[i]; sd[i] = v; mx = fmaxf(mx, v); }
    red[t] = mx; __syncthreads();
    for (int o = 128; o > 0; o >>= 1) { if (t < o) red[t] = fmaxf(red[t], red[t + o]); __syncthreads(); }
    mx = red[0]; __syncthreads();
    float sum = 0.0f;
    for (int i = t; i < K_; i += 256) { float e = expf(sd[i] - mx); sd[i] = e; sum += e; }
    red[t] = sum; __syncthreads();
    for (int o = 128; o > 0; o >>= 1) { if (t < o) red[t] += red[t + o]; __syncthreads(); }
    float inv = 1.0f / red[0];
    for (int i = t; i < K_; i += 256) p[i] = sd[i] * inv;
}

// ---------------- attn_avg = mean over heads -> d_out[32768:] ---------------
__global__ void k_avg(float* __restrict__ out2) {
    int idx = blockIdx.x * blockDim.x + threadIdx.x;  // 131072 total
    int b = idx >> 12, j = idx & 4095;
    float s = 0.0f;
#pragma unroll
    for (int h = 0; h < H_; h++) s += g_attn[((size_t)b * H_ + h) * K_ + j];
    out2[(size_t)b * K_ + j] = s * 0.125f;
}

// ---------------- ctx partials: attn[b,h,:] @ v[:,h,:] over j-split ---------
__global__ void k_ctxpart() {
    int h  = blockIdx.x;       // 8
    int sp = blockIdx.y;       // 16
    int jbase = sp * (K_ / NSPLIT);   // 256 j per split
    __shared__ float As[32][36];    // [j][b]
    __shared__ float Bs[32][128];   // [j][d]
    int t = threadIdx.x;
    float acc[4][4] = {};
    int rm = (t >> 5) * 4, rn = (t & 31) * 4;
    int ab = t >> 3, ajq = (t & 7) * 4;

    for (int k0 = 0; k0 < K_ / NSPLIT; k0 += 32) {
        float4 av = *(const float4*)(g_attn + ((size_t)ab * H_ + h) * K_ + jbase + k0 + ajq);
        As[ajq+0][ab]=av.x; As[ajq+1][ab]=av.y; As[ajq+2][ab]=av.z; As[ajq+3][ab]=av.w;
#pragma unroll
        for (int p = 0; p < 4; p++) {
            int id = t + p * 256;
            int jr = id >> 5, dc = (id & 31) * 4;
            *(float4*)&Bs[jr][dc] =
                *(const float4*)(g_vproj + (size_t)(jbase + k0 + jr) * D_ + h * HD_ + dc);
        }
        __syncthreads();
#pragma unroll
        for (int kk = 0; kk < 32; kk++) {
            float a[4], b[4];
            *(float4*)&a[0] = *(const float4*)&As[kk][rm];
            *(float4*)&b[0] = *(const float4*)&Bs[kk][rn];
#pragma unroll
            for (int i = 0; i < 4; i++)
#pragma unroll
                for (int j = 0; j < 4; j++)
                    acc[i][j] += a[i] * b[j];
        }
        __syncthreads();
    }
#pragma unroll
    for (int i = 0; i < 4; i++)
#pragma unroll
        for (int j = 0; j < 4; j++)
            g_ctx_part[((size_t)sp * B_ + rm + i) * D_ + h * HD_ + rn + j] = acc[i][j];
}

__global__ void k_ctxred() {
    int i = blockIdx.x * blockDim.x + threadIdx.x;  // 32768
    float s = 0.0f;
#pragma unroll
    for (int sp = 0; sp < NSPLIT; sp++) s += g_ctx_part[(size_t)sp * B_ * D_ + i];
    g_ctx[i] = s;
}

// ---------------- launch ----------------
extern "C" void kernel_launch(void* const* d_in, const int* in_sizes, int n_in,
                              void* d_out, int out_size) {
    const float* query  = (const float*)d_in[0];
    const float* buffer = (const float*)d_in[1];
    const float* prio   = (const float*)d_in[2];
    const float* Wq     = (const float*)d_in[3];
    const float* bq     = (const float*)d_in[4];
    const float* Wk     = (const float*)d_in[5];
    const float* bk     = (const float*)d_in[6];
    const float* Wv     = (const float*)d_in[7];
    const float* bv     = (const float*)d_in[8];
    const float* Wo     = (const float*)d_in[9];
    const float* bo     = (const float*)d_in[10];
    float* out = (float*)d_out;   // [0,32768): retrieved, [32768,163840): attn_avg

    cudaFuncSetAttribute(k_kvproj_mma, cudaFuncAttributeMaxDynamicSharedMemorySize,
                         KV_SMEM_BYTES);

    // selection + weight pre-convert (cvtW independent of selection)
    k_zero16<<<64, 256>>>();
    k_hist16<<<64, 256>>>(prio);
    k_cvtW<<<dim3(32, 32, 2), dim3(32, 8)>>>(Wk, Wv);
    k_findbin<<<1, 1024>>>();
    k_compact16<<<64, 256>>>(prio);
    k_selfin48<<<1, 256>>>();
    k_rank<<<K_ / 8, 256>>>();
    k_gatherA<<<K_, 256>>>(buffer);

    // K/V projection on tensor cores (fp16 mma, cp.async 3-stage pipeline)
    k_kvproj_mma<<<dim3(8, 32, 2), 256, KV_SMEM_BYTES>>>(bk, bv);

    // attention tail (q projection via split-K)
    k_gemm32s<<<dim3(8, GSPLIT), 256>>>(query, Wq, 0);
    k_gemmred<<<128, 256>>>(bq, nullptr, 0);
    k_scores<<<dim3(32, 8), 256>>>();
    k_softmax<<<256, 256>>>();
    k_avg<<<512, 256>>>(out + B_ * D_);
    k_ctxpart<<<dim3(8, NSPLIT), 256>>>();
    k_ctxred<<<128, 256>>>();
    k_gemm32s<<<dim3(8, GSPLIT), 256>>>(nullptr, Wo, 1);   // output projection
    k_gemmred<<<128, 256>>>(bo, out, 1);
}

// round 14
// speedup vs baseline: 1.6479x; 1.0908x over previous
#include <cuda_runtime.h>
#include <cuda_fp16.h>
#include <math.h>
#include <stdint.h>

// Problem constants (fixed by the dataset)
#define B_   32
#define D_   1024
#define N_   65536
#define K_   4096
#define H_   8
#define HD_  128
#define NSPLIT 16
#define GSPLIT 4

typedef unsigned long long u64;
typedef unsigned int       u32;

// ---------------- scratch (static device globals; no allocation) -------------
__device__ u32  g_hist16[65536];
__device__ u32  g_strip[1024];      // coarse histogram: bin >> 6
__device__ int  g_T16;
__device__ int  g_cumAbove;
__device__ int  g_num_cand;
__device__ int  g_sel_count;
__device__ u64  g_cand[N_];
__device__ u64  g_sel_ck[K_];
__device__ int  g_sorted_idx[K_];
__device__ __half g_WkH[D_ * D_];   // W^T as fp16: [n][k]
__device__ __half g_WvH[D_ * D_];
__device__ __half g_aH[K_ * D_];    // gathered rows as fp16: [m][k]
__device__ float g_kproj[K_ * D_];
__device__ float g_vproj[K_ * D_];
__device__ float g_qproj[B_ * D_];
__device__ float g_attn[B_ * H_ * K_];
__device__ float g_ctx_part[NSPLIT * B_ * D_];
__device__ float g_ctx[B_ * D_];
__device__ float g_gpart[GSPLIT * B_ * D_];

// m16n8k16 fp16 MMA, fp32 accum (base PTX, sm_80+; no sm_103a-gated features)
__device__ __forceinline__ void mma_f16(
    float& c0, float& c1, float& c2, float& c3,
    u32 a0, u32 a1, u32 a2, u32 a3, u32 b0, u32 b1)
{
    asm volatile(
        "mma.sync.aligned.m16n8k16.row.col.f32.f16.f16.f32 "
        "{%0,%1,%2,%3}, {%4,%5,%6,%7}, {%8,%9}, {%0,%1,%2,%3};"
        : "+f"(c0), "+f"(c1), "+f"(c2), "+f"(c3)
        : "r"(a0), "r"(a1), "r"(a2), "r"(a3), "r"(b0), "r"(b1));
}

__device__ __forceinline__ u32 smem_u32(const void* p) {
    u32 a;
    asm("{ .reg .u64 t; cvta.to.shared.u64 t, %1; cvt.u32.u64 %0, t; }" : "=r"(a) : "l"(p));
    return a;
}
__device__ __forceinline__ void cp_async16(u32 dst, const void* src) {
    asm volatile("cp.async.ca.shared.global [%0], [%1], 16;" :: "r"(dst), "l"(src));
}
#define CP_COMMIT() asm volatile("cp.async.commit_group;" ::: "memory")
#define CP_WAIT1()  asm volatile("cp.async.wait_group 1;" ::: "memory")

// Composite key: (monotone(float) << 32) | (0xFFFFFFFF - index)
// Descending composite order == (value desc, index asc) == jax.lax.top_k order.
__device__ __forceinline__ u64 make_ck(float f, int i) {
    u32 x = __float_as_uint(f);
    u32 t = (x & 0x80000000u) ? ~x : (x | 0x80000000u);
    return ((u64)t << 32) | (u32)(0xFFFFFFFFu - (u32)i);
}

// ---------------- selection ----------------
__global__ void k_zero16() {
    int stride = gridDim.x * blockDim.x;
    int gtid = blockIdx.x * blockDim.x + threadIdx.x;
    for (int i = gtid; i < 65536; i += stride)
        g_hist16[i] = 0;
    if (gtid < 1024) g_strip[gtid] = 0;
    if (gtid == 0) { g_num_cand = 0; g_sel_count = 0; }
}

__global__ void k_hist16(const float* __restrict__ prio) {
    int stride = gridDim.x * blockDim.x;
    for (int i = blockIdx.x * blockDim.x + threadIdx.x; i < N_; i += stride) {
        u64 ck = make_ck(prio[i], i);
        u32 bin = (u32)(ck >> 48);
        atomicAdd(&g_hist16[bin], 1u);
        atomicAdd(&g_strip[bin >> 6], 1u);
    }
}

// Single CTA, 1024 threads: find the 16-bit threshold bin. Fully parallel:
// strip histogram (precomputed) + Hillis-Steele scan + parallel boundary pick.
__global__ void k_findbin() {
    __shared__ u32 strip[1024];
    __shared__ u32 arr[64];
    __shared__ int s_st;
    __shared__ u32 s_cum;
    int t = threadIdx.x;

    strip[t] = g_strip[1023 - t];
    __syncthreads();

    for (int off = 1; off < 1024; off <<= 1) {
        u32 v = strip[t];
        u32 a = (t >= off) ? strip[t - off] : 0u;
        __syncthreads();
        strip[t] = v + a;
        __syncthreads();
    }

    {
        u32 inc  = strip[t];
        u32 prev = (t == 0) ? 0u : strip[t - 1];
        if (inc >= (u32)K_ && prev < (u32)K_) { s_st = t; s_cum = prev; }
    }
    __syncthreads();

    int st = s_st;
    u32 cum = s_cum;
    if (t < 64) arr[t] = g_hist16[65535 - 64 * st - t];
    __syncthreads();
    for (int off = 1; off < 64; off <<= 1) {
        u32 v = (t < 64) ? arr[t] : 0u;
        u32 a = (t < 64 && t >= off) ? arr[t - off] : 0u;
        __syncthreads();
        if (t < 64) arr[t] = v + a;
        __syncthreads();
    }
    if (t < 64) {
        u32 R    = (u32)K_ - cum;
        u32 inc  = arr[t];
        u32 prev = (t == 0) ? 0u : arr[t - 1];
        if (inc >= R && prev < R) {
            g_T16 = 65535 - 64 * st - t;
            g_cumAbove = (int)(cum + prev);
        }
    }
}

__global__ void k_compact16(const float* __restrict__ prio) {
    int T16 = g_T16;
    int stride = gridDim.x * blockDim.x;
    for (int i = blockIdx.x * blockDim.x + threadIdx.x; i < N_; i += stride) {
        u64 ck = make_ck(prio[i], i);
        int k16 = (int)(u32)(ck >> 48);
        if (k16 > T16) {
            int p = atomicAdd(&g_sel_count, 1);
            g_sel_ck[p] = ck;
        } else if (k16 == T16) {
            int p = atomicAdd(&g_num_cand, 1);
            g_cand[p] = ck;
        }
    }
}

// Single CTA: refine the low 48 bits among the (tiny) candidate set.
__global__ void k_selfin48() {
    __shared__ u64 sc[4096];
    __shared__ u32 hist[256];
    __shared__ u64 s_pref;
    __shared__ int s_R;
    int t = threadIdx.x;  // 256
    int nc = g_num_cand;
    bool inSm = (nc <= 4096);
    if (inSm) for (int i = t; i < nc; i += 256) sc[i] = g_cand[i];
    if (t == 0) {
        s_pref = ((u64)(u32)g_T16) << 48;
        s_R = K_ - g_cumAbove;
    }
    __syncthreads();
    for (int shift = 40; shift >= 0; shift -= 8) {
        hist[t] = 0;
        __syncthreads();
        u64 pref  = s_pref;
        u64 hmask = (~0ULL) << (shift + 8);
        for (int i = t; i < nc; i += 256) {
            u64 ck = inSm ? sc[i] : g_cand[i];
            if ((ck & hmask) == pref)
                atomicAdd(&hist[(u32)(ck >> shift) & 0xFFu], 1u);
        }
        __syncthreads();
        if (t == 0) {
            int R = s_R, cum = 0, b = 0;
            for (int bb = 255; bb >= 0; bb--) {
                if (cum + (int)hist[bb] >= R) { b = bb; break; }
                cum += (int)hist[bb];
            }
            s_pref = pref | (((u64)(u32)b) << shift);
            s_R = R - cum;
        }
        __syncthreads();
    }
    u64 T = s_pref;
    for (int i = t; i < nc; i += 256) {
        u64 ck = inSm ? sc[i] : g_cand[i];
        if (ck >= T) {
            int p = atomicAdd(&g_sel_count, 1);
            g_sel_ck[p] = ck;
        }
    }
}

// Rank sort: one warp per selected element, pairwise count of larger keys.
__global__ void k_rank() {
    __shared__ u64 s_ck[K_];  // 32 KB
    int t = threadIdx.x;
    for (int i = t; i < K_; i += blockDim.x) s_ck[i] = g_sel_ck[i];
    __syncthreads();
    int warp = t >> 5, lane = t & 31;
    int i = blockIdx.x * 8 + warp;
    u64 my = s_ck[i];
    int cnt = 0;
    for (int j = lane; j < K_; j += 32)
        cnt += (s_ck[j] > my) ? 1 : 0;
#pragma unroll
    for (int o = 16; o > 0; o >>= 1) cnt += __shfl_down_sync(0xFFFFFFFFu, cnt, o);
    if (lane == 0)
        g_sorted_idx[cnt] = (int)(0xFFFFFFFFu - (u32)(my & 0xFFFFFFFFull));
}

// ---------------- pre-convert W: fp16 transpose WT[n][k] ----------------
__global__ void k_cvtW(const float* __restrict__ Wk, const float* __restrict__ Wv) {
    __shared__ float tile[32][33];
    const float* W = blockIdx.z ? Wv : Wk;
    __half* WT     = blockIdx.z ? g_WvH : g_WkH;
    int n  = blockIdx.x * 32 + threadIdx.x;
    int k0 = blockIdx.y * 32;
    for (int i = threadIdx.y; i < 32; i += 8)
        tile[i][threadIdx.x] = W[(size_t)(k0 + i) * D_ + n];
    __syncthreads();
    int k   = k0 + threadIdx.x;
    int nn0 = blockIdx.x * 32;
    for (int i = threadIdx.y; i < 32; i += 8)
        WT[(size_t)(nn0 + i) * D_ + k] = __float2half_rn(tile[threadIdx.x][i]);
}

// ---------------- pre-gather A rows as fp16 ----------------
__global__ void k_gatherA(const float* __restrict__ buffer) {
    int row = blockIdx.x;                 // 4096
    const float4* src = (const float4*)(buffer + (size_t)g_sorted_idx[row] * D_);
    uint2* dst = (uint2*)(g_aH + (size_t)row * D_);
    int t = threadIdx.x;                  // 256
    float4 v = src[t];
    __half2 h0 = __floats2half2_rn(v.x, v.y);
    __half2 h1 = __floats2half2_rn(v.z, v.w);
    dst[t] = make_uint2(*(u32*)&h0, *(u32*)&h1);
}

// ============ K/V projection: fp16 m16n8k16 + cp.async 3-stage pipeline ======
// CTA tile 128x128, 8 warps, warp tile 64x32 (4x4 frags of 16x8), K chunks of 32.
// z passed as a kernel arg (K-half / V-half launched separately for overlap).
#define KV_CH 32
#define KV_NCH (D_ / KV_CH)            // 32
#define KV_ROW_U32 28
#define KV_STAGE_U32 (2 * 128 * KV_ROW_U32)  // 7168 u32 = 28672 B
#define KV_STAGE_B   (KV_STAGE_U32 * 4)
#define KV_SMEM_BYTES (3 * KV_STAGE_B)       // 86016

__global__ void __launch_bounds__(256, 2)
k_kvproj_mma(const float* __restrict__ bias, int z)
{
    extern __shared__ u32 dsm[];
    u32 sbase = smem_u32(dsm);

    const __half* WH  = z ? g_WvH : g_WkH;
    float* out        = z ? g_vproj : g_kproj;
    int m0 = blockIdx.y * 128;
    int n0 = blockIdx.x * 128;

    int t    = threadIdx.x;
    int lane = t & 31, wid = t >> 5;
    int grp  = lane >> 2, qid = lane & 3;
    int wm   = (wid >> 2) * 64;   // 0 / 64
    int wn   = (wid & 3) * 32;    // 0 / 32 / 64 / 96

    int row = t >> 1, hf = (t & 1) * 32;
    const char* aSrc = (const char*)(g_aH + (size_t)(m0 + row) * D_) + hf;
    const char* bSrc = (const char*)(WH   + (size_t)(n0 + row) * D_) + hf;
    u32 dstA = sbase + (u32)(row * 112 + hf);
    u32 dstB = dstA + (u32)(128 * 112);

#define KV_ISSUE(c) do { \
    u32 _so = (u32)(((c) % 3) * KV_STAGE_B); \
    const char* _as = aSrc + (size_t)(c) * 64; \
    const char* _bs = bSrc + (size_t)(c) * 64; \
    cp_async16(dstA + _so,      _as); \
    cp_async16(dstA + _so + 16, _as + 16); \
    cp_async16(dstB + _so,      _bs); \
    cp_async16(dstB + _so + 16, _bs + 16); \
    CP_COMMIT(); \
} while (0)

    float acc[4][4][4];
#pragma unroll
    for (int i = 0; i < 4; i++)
#pragma unroll
        for (int j = 0; j < 4; j++)
#pragma unroll
            for (int q = 0; q < 4; q++) acc[i][j][q] = 0.0f;

    KV_ISSUE(0);
    KV_ISSUE(1);

    for (int c = 0; c < KV_NCH; c++) {
        CP_WAIT1();
        __syncthreads();
        if (c + 2 < KV_NCH) KV_ISSUE(c + 2);

        const u32* As = dsm + (c % 3) * KV_STAGE_U32;
        const u32* Bs = As + 128 * KV_ROW_U32;
#pragma unroll
        for (int kk = 0; kk < 2; kk++) {
            int kb = kk * 8;
            u32 af[4][4], bf[4][2];
#pragma unroll
            for (int mf = 0; mf < 4; mf++) {
                int r = wm + mf * 16 + grp;
                af[mf][0] = As[r * KV_ROW_U32 + kb + qid];
                af[mf][1] = As[(r + 8) * KV_ROW_U32 + kb + qid];
                af[mf][2] = As[r * KV_ROW_U32 + kb + qid + 4];
                af[mf][3] = As[(r + 8) * KV_ROW_U32 + kb + qid + 4];
            }
#pragma unroll
            for (int nf = 0; nf < 4; nf++) {
                int n = wn + nf * 8 + grp;
                bf[nf][0] = Bs[n * KV_ROW_U32 + kb + qid];
                bf[nf][1] = Bs[n * KV_ROW_U32 + kb + qid + 4];
            }
#pragma unroll
            for (int mf = 0; mf < 4; mf++)
#pragma unroll
                for (int nf = 0; nf < 4; nf++)
                    mma_f16(acc[mf][nf][0], acc[mf][nf][1], acc[mf][nf][2], acc[mf][nf][3],
                            af[mf][0], af[mf][1], af[mf][2], af[mf][3],
                            bf[nf][0], bf[nf][1]);
        }
    }

#pragma unroll
    for (int mf = 0; mf < 4; mf++) {
#pragma unroll
        for (int nf = 0; nf < 4; nf++) {
            int n = n0 + wn + nf * 8 + 2 * qid;
            float bv0 = bias[n], bv1 = bias[n + 1];
            int r0 = m0 + wm + mf * 16 + grp;
            float2 v0 = make_float2(acc[mf][nf][0] + bv0, acc[mf][nf][1] + bv1);
            float2 v1 = make_float2(acc[mf][nf][2] + bv0, acc[mf][nf][3] + bv1);
            *(float2*)(out + (size_t)r0 * D_ + n)       = v0;
            *(float2*)(out + (size_t)(r0 + 8) * D_ + n) = v1;
        }
    }
#undef KV_ISSUE
}

// ---------------- M=32 GEMM, split-K (q proj: mode 0, out proj: mode 1) -----
__global__ void k_gemm32s(const float* __restrict__ Aext,
                          const float* __restrict__ W, int mode)
{
    const float* A = (mode == 0) ? Aext : g_ctx;
    int n0 = blockIdx.x * 128;
    int ks = blockIdx.y * (D_ / GSPLIT);   // 256-wide K slice

    __shared__ float As[32][36];   // [k][b]
    __shared__ float Bs[32][128];  // [k][n]
    int t = threadIdx.x;
    float acc[4][4] = {};
    int rm = (t >> 5) * 4, rn = (t & 31) * 4;
    int ab = t >> 3, akq = (t & 7) * 4;

    for (int k0 = ks; k0 < ks + D_ / GSPLIT; k0 += 32) {
        float4 av = *(const float4*)(A + (size_t)ab * D_ + k0 + akq);
        As[akq+0][ab]=av.x; As[akq+1][ab]=av.y; As[akq+2][ab]=av.z; As[akq+3][ab]=av.w;
#pragma unroll
        for (int p = 0; p < 4; p++) {
            int id = t + p * 256;
            int br = id >> 5, bc = (id & 31) * 4;
            *(float4*)&Bs[br][bc] = *(const float4*)(W + (size_t)(k0 + br) * D_ + n0 + bc);
        }
        __syncthreads();
#pragma unroll
        for (int kk = 0; kk < 32; kk++) {
            float a[4], b[4];
            *(float4*)&a[0] = *(const float4*)&As[kk][rm];
            *(float4*)&b[0] = *(const float4*)&Bs[kk][rn];
#pragma unroll
            for (int i = 0; i < 4; i++)
#pragma unroll
                for (int j = 0; j < 4; j++)
                    acc[i][j] += a[i] * b[j];
        }
        __syncthreads();
    }
#pragma unroll
    for (int i = 0; i < 4; i++) {
        float* op = g_gpart + ((size_t)blockIdx.y * B_ + rm + i) * D_ + n0 + rn;
#pragma unroll
        for (int j = 0; j < 4; j++)
            op[j] = acc[i][j];
    }
}

__global__ void k_gemmred(const float* __restrict__ bias,
                          float* __restrict__ outext, int mode)
{
    float* dst = (mode == 0) ? g_qproj : outext;
    int i = blockIdx.x * blockDim.x + threadIdx.x;  // 32768
    int n = i & (D_ - 1);
    float s = bias[n];
#pragma unroll
    for (int sp = 0; sp < GSPLIT; sp++) s += g_gpart[(size_t)sp * B_ * D_ + i];
    dst[i] = s;
}

// ---------------- scores[b,h,j] = scale * q[b,h,:] . k[j,h,:] ---------------
__global__ void k_scores() {
    int j0 = blockIdx.x * 128;
    int h  = blockIdx.y;
    __shared__ float As[32][36];   // [d][b]
    __shared__ float Bs[32][132];  // [d][j]
    int t = threadIdx.x;
    float acc[4][4] = {};
    int rm = (t >> 5) * 4, rn = (t & 31) * 4;
    int ab = t >> 3, akq = (t & 7) * 4;

    for (int d0 = 0; d0 < HD_; d0 += 32) {
        float4 av = *(const float4*)(g_qproj + (size_t)ab * D_ + h * HD_ + d0 + akq);
        As[akq+0][ab]=av.x; As[akq+1][ab]=av.y; As[akq+2][ab]=av.z; As[akq+3][ab]=av.w;
#pragma unroll
        for (int p = 0; p < 4; p++) {
            int id = t + p * 256;
            int jr = id >> 3, dq = (id & 7) * 4;
            float4 bvv = *(const float4*)(g_kproj + (size_t)(j0 + jr) * D_ + h * HD_ + d0 + dq);
            Bs[dq+0][jr]=bvv.x; Bs[dq+1][jr]=bvv.y; Bs[dq+2][jr]=bvv.z; Bs[dq+3][jr]=bvv.w;
        }
        __syncthreads();
#pragma unroll
        for (int kk = 0; kk < 32; kk++) {
            float a[4], b[4];
            *(float4*)&a[0] = *(const float4*)&As[kk][rm];
            *(float4*)&b[0] = *(const float4*)&Bs[kk][rn];
#pragma unroll
            for (int i = 0; i < 4; i++)
#pragma unroll
                for (int j = 0; j < 4; j++)
                    acc[i][j] += a[i] * b[j];
        }
        __syncthreads();
    }
    const float scale = 0.08838834764831845f;  // 128^-0.5
#pragma unroll
    for (int i = 0; i < 4; i++)
#pragma unroll
        for (int j = 0; j < 4; j++)
            g_attn[((size_t)(rm + i) * H_ + h) * K_ + j0 + rn + j] = acc[i][j] * scale;
}

// ---------------- softmax over j (in place), one CTA per (b,h) row ----------
__global__ void k_softmax() {
    int row = blockIdx.x;
    float* p = g_attn + (size_t)row * K_;
    __shared__ float sd[K_];
    __shared__ float red[256];
    int t = threadIdx.x;
    float mx = -1e30f;
    for (int i = t; i < K_; i += 256) { float v = p[i]; sd[i] = v; mx = fmaxf(mx, v); }
    red[t] = mx; __syncthreads();
    for (int o = 128; o > 0; o >>= 1) { if (t < o) red[t] = fmaxf(red[t], red[t + o]); __syncthreads(); }
    mx = red[0]; __syncthreads();
    float sum = 0.0f;
    for (int i = t; i < K_; i += 256) { float e = expf(sd[i] - mx); sd[i] = e; sum += e; }
    red[t] = sum; __syncthreads();
    for (int o = 128; o > 0; o >>= 1) { if (t < o) red[t] += red[t + o]; __syncthreads(); }
    float inv = 1.0f / red[0];
    for (int i = t; i < K_; i += 256) p[i] = sd[i] * inv;
}

// ---------------- attn_avg = mean over heads -> d_out[32768:] ---------------
__global__ void k_avg(float* __restrict__ out2) {
    int idx = blockIdx.x * blockDim.x + threadIdx.x;  // 131072 total
    int b = idx >> 12, j = idx & 4095;
    float s = 0.0f;
#pragma unroll
    for (int h = 0; h < H_; h++) s += g_attn[((size_t)b * H_ + h) * K_ + j];
    out2[(size_t)b * K_ + j] = s * 0.125f;
}

// ---------------- ctx partials: attn[b,h,:] @ v[:,h,:] over j-split ---------
__global__ void k_ctxpart() {
    int h  = blockIdx.x;       // 8
    int sp = blockIdx.y;       // 16
    int jbase = sp * (K_ / NSPLIT);   // 256 j per split
    __shared__ float As[32][36];    // [j][b]
    __shared__ float Bs[32][128];   // [j][d]
    int t = threadIdx.x;
    float acc[4][4] = {};
    int rm = (t >> 5) * 4, rn = (t & 31) * 4;
    int ab = t >> 3, ajq = (t & 7) * 4;

    for (int k0 = 0; k0 < K_ / NSPLIT; k0 += 32) {
        float4 av = *(const float4*)(g_attn + ((size_t)ab * H_ + h) * K_ + jbase + k0 + ajq);
        As[ajq+0][ab]=av.x; As[ajq+1][ab]=av.y; As[ajq+2][ab]=av.z; As[ajq+3][ab]=av.w;
#pragma unroll
        for (int p = 0; p < 4; p++) {
            int id = t + p * 256;
            int jr = id >> 5, dc = (id & 31) * 4;
            *(float4*)&Bs[jr][dc] =
                *(const float4*)(g_vproj + (size_t)(jbase + k0 + jr) * D_ + h * HD_ + dc);
        }
        __syncthreads();
#pragma unroll
        for (int kk = 0; kk < 32; kk++) {
            float a[4], b[4];
            *(float4*)&a[0] = *(const float4*)&As[kk][rm];
            *(float4*)&b[0] = *(const float4*)&Bs[kk][rn];
#pragma unroll
            for (int i = 0; i < 4; i++)
#pragma unroll
                for (int j = 0; j < 4; j++)
                    acc[i][j] += a[i] * b[j];
        }
        __syncthreads();
    }
#pragma unroll
    for (int i = 0; i < 4; i++)
#pragma unroll
        for (int j = 0; j < 4; j++)
            g_ctx_part[((size_t)sp * B_ + rm + i) * D_ + h * HD_ + rn + j] = acc[i][j];
}

__global__ void k_ctxred() {
    int i = blockIdx.x * blockDim.x + threadIdx.x;  // 32768
    float s = 0.0f;
#pragma unroll
    for (int sp = 0; sp < NSPLIT; sp++) s += g_ctx_part[(size_t)sp * B_ * D_ + i];
    g_ctx[i] = s;
}

// ---------------- launch (fork/join stream DAG, graph-capturable) ----------
extern "C" void kernel_launch(void* const* d_in, const int* in_sizes, int n_in,
                              void* d_out, int out_size) {
    const float* query  = (const float*)d_in[0];
    const float* buffer = (const float*)d_in[1];
    const float* prio   = (const float*)d_in[2];
    const float* Wq     = (const float*)d_in[3];
    const float* bq     = (const float*)d_in[4];
    const float* Wk     = (const float*)d_in[5];
    const float* bk     = (const float*)d_in[6];
    const float* Wv     = (const float*)d_in[7];
    const float* bv     = (const float*)d_in[8];
    const float* Wo     = (const float*)d_in[9];
    const float* bo     = (const float*)d_in[10];
    float* out = (float*)d_out;   // [0,32768): retrieved, [32768,163840): attn_avg

    // Lazily created ONCE on the first (uncaptured correctness) call and
    // reused forever — so all driver-side allocations happen before the
    // harness's pre-capture memory baseline and nothing is allocated during
    // capture or leaked after graph teardown. The launch sequence below is
    // identical on every call.
    static cudaStream_t s2 = nullptr, s3 = nullptr;
    static cudaEvent_t eFork = nullptr, eQdone = nullptr, eKdone = nullptr, eAttn = nullptr;
    if (s2 == nullptr) {
        cudaStreamCreateWithFlags(&s2, cudaStreamNonBlocking);
        cudaStreamCreateWithFlags(&s3, cudaStreamNonBlocking);
        cudaEventCreateWithFlags(&eFork,  cudaEventDisableTiming);
        cudaEventCreateWithFlags(&eQdone, cudaEventDisableTiming);
        cudaEventCreateWithFlags(&eKdone, cudaEventDisableTiming);
        cudaEventCreateWithFlags(&eAttn,  cudaEventDisableTiming);
        cudaFuncSetAttribute(k_kvproj_mma, cudaFuncAttributeMaxDynamicSharedMemorySize,
                             KV_SMEM_BYTES);
    }

    // ---- fork s2: weight pre-convert + q projection (independent of selection)
    cudaEventRecord(eFork, 0);
    cudaStreamWaitEvent(s2, eFork, 0);
    k_cvtW<<<dim3(32, 32, 2), dim3(32, 8), 0, s2>>>(Wk, Wv);
    k_gemm32s<<<dim3(8, GSPLIT), 256, 0, s2>>>(query, Wq, 0);
    k_gemmred<<<128, 256, 0, s2>>>(bq, nullptr, 0);
    cudaEventRecord(eQdone, s2);

    // ---- main stream: selection chain + gather
    k_zero16<<<64, 256>>>();
    k_hist16<<<64, 256>>>(prio);
    k_findbin<<<1, 1024>>>();
    k_compact16<<<64, 256>>>(prio);
    k_selfin48<<<1, 256>>>();
    k_rank<<<K_ / 8, 256>>>();
    k_gatherA<<<K_, 256>>>(buffer);

    // join s2 (kvproj needs g_WkH/g_WvH; scores later needs g_qproj)
    cudaStreamWaitEvent(0, eQdone, 0);

    // K projection, then V projection overlapped with attention-score chain
    k_kvproj_mma<<<dim3(8, 32), 256, KV_SMEM_BYTES>>>(bk, 0);
    cudaEventRecord(eKdone, 0);
    k_kvproj_mma<<<dim3(8, 32), 256, KV_SMEM_BYTES>>>(bv, 1);

    // ---- fork s3: scores -> softmax -> avg (needs kproj + qproj only)
    cudaStreamWaitEvent(s3, eKdone, 0);
    k_scores<<<dim3(32, 8), 256, 0, s3>>>();
    k_softmax<<<256, 256, 0, s3>>>();
    k_avg<<<512, 256, 0, s3>>>(out + B_ * D_);
    cudaEventRecord(eAttn, s3);

    // join s3; ctx needs attn + vproj
    cudaStreamWaitEvent(0, eAttn, 0);
    k_ctxpart<<<dim3(8, NSPLIT), 256>>>();
    k_ctxred<<<128, 256>>>();
    k_gemm32s<<<dim3(8, GSPLIT), 256>>>(nullptr, Wo, 1);   // output projection
    k_gemmred<<<128, 256>>>(bo, out, 1);
}

// round 15
// speedup vs baseline: 1.7203x; 1.0439x over previous
#include <cuda_runtime.h>
#include <cuda_fp16.h>
#include <math.h>
#include <stdint.h>

// Problem constants (fixed by the dataset)
#define B_   32
#define D_   1024
#define N_   65536
#define K_   4096
#define H_   8
#define HD_  128
#define NSPLIT 16
#define GSPLIT 4

typedef unsigned long long u64;
typedef unsigned int       u32;

// ---------------- scratch (static device globals; no allocation) -------------
__device__ u32  g_hist16[65536];
__device__ u32  g_strip[1024];      // coarse histogram: bin >> 6
__device__ int  g_T16;
__device__ int  g_cumAbove;
__device__ int  g_num_cand;
__device__ int  g_sel_count;
__device__ u64  g_cand[N_];
__device__ u64  g_sel_ck[K_];
__device__ int  g_sorted_idx[K_];
__device__ __half g_WkH[D_ * D_];   // W^T as fp16: [n][k]
__device__ __half g_WvH[D_ * D_];
__device__ __half g_aH[K_ * D_];    // gathered rows as fp16: [m][k]
__device__ float g_kproj[K_ * D_];
__device__ float g_vproj[K_ * D_];
__device__ float g_qproj[B_ * D_];
__device__ float g_attn[B_ * H_ * K_];
__device__ float g_ctx_part[NSPLIT * B_ * D_];
__device__ float g_ctx[B_ * D_];
__device__ float g_gpart[GSPLIT * B_ * D_];

// m16n8k16 fp16 MMA, fp32 accum (base PTX, sm_80+; no sm_103a-gated features)
__device__ __forceinline__ void mma_f16(
    float& c0, float& c1, float& c2, float& c3,
    u32 a0, u32 a1, u32 a2, u32 a3, u32 b0, u32 b1)
{
    asm volatile(
        "mma.sync.aligned.m16n8k16.row.col.f32.f16.f16.f32 "
        "{%0,%1,%2,%3}, {%4,%5,%6,%7}, {%8,%9}, {%0,%1,%2,%3};"
        : "+f"(c0), "+f"(c1), "+f"(c2), "+f"(c3)
        : "r"(a0), "r"(a1), "r"(a2), "r"(a3), "r"(b0), "r"(b1));
}

__device__ __forceinline__ u32 smem_u32(const void* p) {
    u32 a;
    asm("{ .reg .u64 t; cvta.to.shared.u64 t, %1; cvt.u32.u64 %0, t; }" : "=r"(a) : "l"(p));
    return a;
}
__device__ __forceinline__ void cp_async16(u32 dst, const void* src) {
    asm volatile("cp.async.ca.shared.global [%0], [%1], 16;" :: "r"(dst), "l"(src));
}
#define CP_COMMIT() asm volatile("cp.async.commit_group;" ::: "memory")
#define CP_WAIT1()  asm volatile("cp.async.wait_group 1;" ::: "memory")

// Composite key: (monotone(float) << 32) | (0xFFFFFFFF - index)
// Descending composite order == (value desc, index asc) == jax.lax.top_k order.
__device__ __forceinline__ u64 make_ck(float f, int i) {
    u32 x = __float_as_uint(f);
    u32 t = (x & 0x80000000u) ? ~x : (x | 0x80000000u);
    return ((u64)t << 32) | (u32)(0xFFFFFFFFu - (u32)i);
}

// ---------------- selection ----------------
__global__ void k_zero16() {
    int stride = gridDim.x * blockDim.x;
    int gtid = blockIdx.x * blockDim.x + threadIdx.x;
    for (int i = gtid; i < 65536; i += stride)
        g_hist16[i] = 0;
    if (gtid < 1024) g_strip[gtid] = 0;
    if (gtid == 0) { g_num_cand = 0; g_sel_count = 0; }
}

__global__ void k_hist16(const float* __restrict__ prio) {
    int stride = gridDim.x * blockDim.x;
    for (int i = blockIdx.x * blockDim.x + threadIdx.x; i < N_; i += stride) {
        u64 ck = make_ck(prio[i], i);
        u32 bin = (u32)(ck >> 48);
        atomicAdd(&g_hist16[bin], 1u);
        atomicAdd(&g_strip[bin >> 6], 1u);
    }
}

// Single CTA, 1024 threads: find the 16-bit threshold bin. Fully parallel:
// strip histogram (precomputed) + Hillis-Steele scan + parallel boundary pick.
__global__ void k_findbin() {
    __shared__ u32 strip[1024];
    __shared__ u32 arr[64];
    __shared__ int s_st;
    __shared__ u32 s_cum;
    int t = threadIdx.x;

    strip[t] = g_strip[1023 - t];
    __syncthreads();

    for (int off = 1; off < 1024; off <<= 1) {
        u32 v = strip[t];
        u32 a = (t >= off) ? strip[t - off] : 0u;
        __syncthreads();
        strip[t] = v + a;
        __syncthreads();
    }

    {
        u32 inc  = strip[t];
        u32 prev = (t == 0) ? 0u : strip[t - 1];
        if (inc >= (u32)K_ && prev < (u32)K_) { s_st = t; s_cum = prev; }
    }
    __syncthreads();

    int st = s_st;
    u32 cum = s_cum;
    if (t < 64) arr[t] = g_hist16[65535 - 64 * st - t];
    __syncthreads();
    for (int off = 1; off < 64; off <<= 1) {
        u32 v = (t < 64) ? arr[t] : 0u;
        u32 a = (t < 64 && t >= off) ? arr[t - off] : 0u;
        __syncthreads();
        if (t < 64) arr[t] = v + a;
        __syncthreads();
    }
    if (t < 64) {
        u32 R    = (u32)K_ - cum;
        u32 inc  = arr[t];
        u32 prev = (t == 0) ? 0u : arr[t - 1];
        if (inc >= R && prev < R) {
            g_T16 = 65535 - 64 * st - t;
            g_cumAbove = (int)(cum + prev);
        }
    }
}

__global__ void k_compact16(const float* __restrict__ prio) {
    int T16 = g_T16;
    int stride = gridDim.x * blockDim.x;
    for (int i = blockIdx.x * blockDim.x + threadIdx.x; i < N_; i += stride) {
        u64 ck = make_ck(prio[i], i);
        int k16 = (int)(u32)(ck >> 48);
        if (k16 > T16) {
            int p = atomicAdd(&g_sel_count, 1);
            g_sel_ck[p] = ck;
        } else if (k16 == T16) {
            int p = atomicAdd(&g_num_cand, 1);
            g_cand[p] = ck;
        }
    }
}

// Single CTA: refine the low 48 bits among the (tiny) candidate set.
__global__ void k_selfin48() {
    __shared__ u64 sc[4096];
    __shared__ u32 hist[256];
    __shared__ u64 s_pref;
    __shared__ int s_R;
    int t = threadIdx.x;  // 256
    int nc = g_num_cand;
    bool inSm = (nc <= 4096);
    if (inSm) for (int i = t; i < nc; i += 256) sc[i] = g_cand[i];
    if (t == 0) {
        s_pref = ((u64)(u32)g_T16) << 48;
        s_R = K_ - g_cumAbove;
    }
    __syncthreads();
    for (int shift = 40; shift >= 0; shift -= 8) {
        hist[t] = 0;
        __syncthreads();
        u64 pref  = s_pref;
        u64 hmask = (~0ULL) << (shift + 8);
        for (int i = t; i < nc; i += 256) {
            u64 ck = inSm ? sc[i] : g_cand[i];
            if ((ck & hmask) == pref)
                atomicAdd(&hist[(u32)(ck >> shift) & 0xFFu], 1u);
        }
        __syncthreads();
        if (t == 0) {
            int R = s_R, cum = 0, b = 0;
            for (int bb = 255; bb >= 0; bb--) {
                if (cum + (int)hist[bb] >= R) { b = bb; break; }
                cum += (int)hist[bb];
            }
            s_pref = pref | (((u64)(u32)b) << shift);
            s_R = R - cum;
        }
        __syncthreads();
    }
    u64 T = s_pref;
    for (int i = t; i < nc; i += 256) {
        u64 ck = inSm ? sc[i] : g_cand[i];
        if (ck >= T) {
            int p = atomicAdd(&g_sel_count, 1);
            g_sel_ck[p] = ck;
        }
    }
}

// Rank sort: one warp per selected element, pairwise count of larger keys.
__global__ void k_rank() {
    __shared__ u64 s_ck[K_];  // 32 KB
    int t = threadIdx.x;
    for (int i = t; i < K_; i += blockDim.x) s_ck[i] = g_sel_ck[i];
    __syncthreads();
    int warp = t >> 5, lane = t & 31;
    int i = blockIdx.x * 8 + warp;
    u64 my = s_ck[i];
    int cnt = 0;
    for (int j = lane; j < K_; j += 32)
        cnt += (s_ck[j] > my) ? 1 : 0;
#pragma unroll
    for (int o = 16; o > 0; o >>= 1) cnt += __shfl_down_sync(0xFFFFFFFFu, cnt, o);
    if (lane == 0)
        g_sorted_idx[cnt] = (int)(0xFFFFFFFFu - (u32)(my & 0xFFFFFFFFull));
}

// ---------------- pre-convert W: fp16 transpose WT[n][k] ----------------
__global__ void k_cvtW(const float* __restrict__ Wk, const float* __restrict__ Wv) {
    __shared__ float tile[32][33];
    const float* W = blockIdx.z ? Wv : Wk;
    __half* WT     = blockIdx.z ? g_WvH : g_WkH;
    int n  = blockIdx.x * 32 + threadIdx.x;
    int k0 = blockIdx.y * 32;
    for (int i = threadIdx.y; i < 32; i += 8)
        tile[i][threadIdx.x] = W[(size_t)(k0 + i) * D_ + n];
    __syncthreads();
    int k   = k0 + threadIdx.x;
    int nn0 = blockIdx.x * 32;
    for (int i = threadIdx.y; i < 32; i += 8)
        WT[(size_t)(nn0 + i) * D_ + k] = __float2half_rn(tile[threadIdx.x][i]);
}

// ---------------- pre-gather A rows as fp16 ----------------
__global__ void k_gatherA(const float* __restrict__ buffer) {
    int row = blockIdx.x;                 // 4096
    const float4* src = (const float4*)(buffer + (size_t)g_sorted_idx[row] * D_);
    uint2* dst = (uint2*)(g_aH + (size_t)row * D_);
    int t = threadIdx.x;                  // 256
    float4 v = src[t];
    __half2 h0 = __floats2half2_rn(v.x, v.y);
    __half2 h1 = __floats2half2_rn(v.z, v.w);
    dst[t] = make_uint2(*(u32*)&h0, *(u32*)&h1);
}

// ============ K/V projection: fp16 m16n8k16 + cp.async 3-stage pipeline ======
// CTA tile 128x128, 8 warps, warp tile 64x32 (4x4 frags of 16x8), K chunks of 32.
// z passed as a kernel arg (K-half / V-half launched concurrently for overlap).
#define KV_CH 32
#define KV_NCH (D_ / KV_CH)            // 32
#define KV_ROW_U32 28
#define KV_STAGE_U32 (2 * 128 * KV_ROW_U32)  // 7168 u32 = 28672 B
#define KV_STAGE_B   (KV_STAGE_U32 * 4)
#define KV_SMEM_BYTES (3 * KV_STAGE_B)       // 86016

__global__ void __launch_bounds__(256, 2)
k_kvproj_mma(const float* __restrict__ bias, int z)
{
    extern __shared__ u32 dsm[];
    u32 sbase = smem_u32(dsm);

    const __half* WH  = z ? g_WvH : g_WkH;
    float* out        = z ? g_vproj : g_kproj;
    int m0 = blockIdx.y * 128;
    int n0 = blockIdx.x * 128;

    int t    = threadIdx.x;
    int lane = t & 31, wid = t >> 5;
    int grp  = lane >> 2, qid = lane & 3;
    int wm   = (wid >> 2) * 64;   // 0 / 64
    int wn   = (wid & 3) * 32;    // 0 / 32 / 64 / 96

    int row = t >> 1, hf = (t & 1) * 32;
    const char* aSrc = (const char*)(g_aH + (size_t)(m0 + row) * D_) + hf;
    const char* bSrc = (const char*)(WH   + (size_t)(n0 + row) * D_) + hf;
    u32 dstA = sbase + (u32)(row * 112 + hf);
    u32 dstB = dstA + (u32)(128 * 112);

#define KV_ISSUE(c) do { \
    u32 _so = (u32)(((c) % 3) * KV_STAGE_B); \
    const char* _as = aSrc + (size_t)(c) * 64; \
    const char* _bs = bSrc + (size_t)(c) * 64; \
    cp_async16(dstA + _so,      _as); \
    cp_async16(dstA + _so + 16, _as + 16); \
    cp_async16(dstB + _so,      _bs); \
    cp_async16(dstB + _so + 16, _bs + 16); \
    CP_COMMIT(); \
} while (0)

    float acc[4][4][4];
#pragma unroll
    for (int i = 0; i < 4; i++)
#pragma unroll
        for (int j = 0; j < 4; j++)
#pragma unroll
            for (int q = 0; q < 4; q++) acc[i][j][q] = 0.0f;

    KV_ISSUE(0);
    KV_ISSUE(1);

    for (int c = 0; c < KV_NCH; c++) {
        CP_WAIT1();
        __syncthreads();
        if (c + 2 < KV_NCH) KV_ISSUE(c + 2);

        const u32* As = dsm + (c % 3) * KV_STAGE_U32;
        const u32* Bs = As + 128 * KV_ROW_U32;
#pragma unroll
        for (int kk = 0; kk < 2; kk++) {
            int kb = kk * 8;
            u32 af[4][4], bf[4][2];
#pragma unroll
            for (int mf = 0; mf < 4; mf++) {
                int r = wm + mf * 16 + grp;
                af[mf][0] = As[r * KV_ROW_U32 + kb + qid];
                af[mf][1] = As[(r + 8) * KV_ROW_U32 + kb + qid];
                af[mf][2] = As[r * KV_ROW_U32 + kb + qid + 4];
                af[mf][3] = As[(r + 8) * KV_ROW_U32 + kb + qid + 4];
            }
#pragma unroll
            for (int nf = 0; nf < 4; nf++) {
                int n = wn + nf * 8 + grp;
                bf[nf][0] = Bs[n * KV_ROW_U32 + kb + qid];
                bf[nf][1] = Bs[n * KV_ROW_U32 + kb + qid + 4];
            }
#pragma unroll
            for (int mf = 0; mf < 4; mf++)
#pragma unroll
                for (int nf = 0; nf < 4; nf++)
                    mma_f16(acc[mf][nf][0], acc[mf][nf][1], acc[mf][nf][2], acc[mf][nf][3],
                            af[mf][0], af[mf][1], af[mf][2], af[mf][3],
                            bf[nf][0], bf[nf][1]);
        }
    }

#pragma unroll
    for (int mf = 0; mf < 4; mf++) {
#pragma unroll
        for (int nf = 0; nf < 4; nf++) {
            int n = n0 + wn + nf * 8 + 2 * qid;
            float bv0 = bias[n], bv1 = bias[n + 1];
            int r0 = m0 + wm + mf * 16 + grp;
            float2 v0 = make_float2(acc[mf][nf][0] + bv0, acc[mf][nf][1] + bv1);
            float2 v1 = make_float2(acc[mf][nf][2] + bv0, acc[mf][nf][3] + bv1);
            *(float2*)(out + (size_t)r0 * D_ + n)       = v0;
            *(float2*)(out + (size_t)(r0 + 8) * D_ + n) = v1;
        }
    }
#undef KV_ISSUE
}

// ---------------- M=32 GEMM, split-K (q proj: mode 0, out proj: mode 1) -----
__global__ void k_gemm32s(const float* __restrict__ Aext,
                          const float* __restrict__ W, int mode)
{
    const float* A = (mode == 0) ? Aext : g_ctx;
    int n0 = blockIdx.x * 128;
    int ks = blockIdx.y * (D_ / GSPLIT);   // 256-wide K slice

    __shared__ float As[32][36];   // [k][b]
    __shared__ float Bs[32][128];  // [k][n]
    int t = threadIdx.x;
    float acc[4][4] = {};
    int rm = (t >> 5) * 4, rn = (t & 31) * 4;
    int ab = t >> 3, akq = (t & 7) * 4;

    for (int k0 = ks; k0 < ks + D_ / GSPLIT; k0 += 32) {
        float4 av = *(const float4*)(A + (size_t)ab * D_ + k0 + akq);
        As[akq+0][ab]=av.x; As[akq+1][ab]=av.y; As[akq+2][ab]=av.z; As[akq+3][ab]=av.w;
#pragma unroll
        for (int p = 0; p < 4; p++) {
            int id = t + p * 256;
            int br = id >> 5, bc = (id & 31) * 4;
            *(float4*)&Bs[br][bc] = *(const float4*)(W + (size_t)(k0 + br) * D_ + n0 + bc);
        }
        __syncthreads();
#pragma unroll
        for (int kk = 0; kk < 32; kk++) {
            float a[4], b[4];
            *(float4*)&a[0] = *(const float4*)&As[kk][rm];
            *(float4*)&b[0] = *(const float4*)&Bs[kk][rn];
#pragma unroll
            for (int i = 0; i < 4; i++)
#pragma unroll
                for (int j = 0; j < 4; j++)
                    acc[i][j] += a[i] * b[j];
        }
        __syncthreads();
    }
#pragma unroll
    for (int i = 0; i < 4; i++) {
        float* op = g_gpart + ((size_t)blockIdx.y * B_ + rm + i) * D_ + n0 + rn;
#pragma unroll
        for (int j = 0; j < 4; j++)
            op[j] = acc[i][j];
    }
}

__global__ void k_gemmred(const float* __restrict__ bias,
                          float* __restrict__ outext, int mode)
{
    float* dst = (mode == 0) ? g_qproj : outext;
    int i = blockIdx.x * blockDim.x + threadIdx.x;  // 32768
    int n = i & (D_ - 1);
    float s = bias[n];
#pragma unroll
    for (int sp = 0; sp < GSPLIT; sp++) s += g_gpart[(size_t)sp * B_ * D_ + i];
    dst[i] = s;
}

// ---------------- scores[b,h,j] = scale * q[b,h,:] . k[j,h,:] ---------------
__global__ void k_scores() {
    int j0 = blockIdx.x * 128;
    int h  = blockIdx.y;
    __shared__ float As[32][36];   // [d][b]
    __shared__ float Bs[32][132];  // [d][j]
    int t = threadIdx.x;
    float acc[4][4] = {};
    int rm = (t >> 5) * 4, rn = (t & 31) * 4;
    int ab = t >> 3, akq = (t & 7) * 4;

    for (int d0 = 0; d0 < HD_; d0 += 32) {
        float4 av = *(const float4*)(g_qproj + (size_t)ab * D_ + h * HD_ + d0 + akq);
        As[akq+0][ab]=av.x; As[akq+1][ab]=av.y; As[akq+2][ab]=av.z; As[akq+3][ab]=av.w;
#pragma unroll
        for (int p = 0; p < 4; p++) {
            int id = t + p * 256;
            int jr = id >> 3, dq = (id & 7) * 4;
            float4 bvv = *(const float4*)(g_kproj + (size_t)(j0 + jr) * D_ + h * HD_ + d0 + dq);
            Bs[dq+0][jr]=bvv.x; Bs[dq+1][jr]=bvv.y; Bs[dq+2][jr]=bvv.z; Bs[dq+3][jr]=bvv.w;
        }
        __syncthreads();
#pragma unroll
        for (int kk = 0; kk < 32; kk++) {
            float a[4], b[4];
            *(float4*)&a[0] = *(const float4*)&As[kk][rm];
            *(float4*)&b[0] = *(const float4*)&Bs[kk][rn];
#pragma unroll
            for (int i = 0; i < 4; i++)
#pragma unroll
                for (int j = 0; j < 4; j++)
                    acc[i][j] += a[i] * b[j];
        }
        __syncthreads();
    }
    const float scale = 0.08838834764831845f;  // 128^-0.5
#pragma unroll
    for (int i = 0; i < 4; i++)
#pragma unroll
        for (int j = 0; j < 4; j++)
            g_attn[((size_t)(rm + i) * H_ + h) * K_ + j0 + rn + j] = acc[i][j] * scale;
}

// ---------------- softmax over j (in place), one CTA per (b,h) row ----------
__global__ void k_softmax() {
    int row = blockIdx.x;
    float* p = g_attn + (size_t)row * K_;
    __shared__ float sd[K_];
    __shared__ float red[256];
    int t = threadIdx.x;
    float mx = -1e30f;
    for (int i = t; i < K_; i += 256) { float v = p[i]; sd[i] = v; mx = fmaxf(mx, v); }
    red[t] = mx; __syncthreads();
    for (int o = 128; o > 0; o >>= 1) { if (t < o) red[t] = fmaxf(red[t], red[t + o]); __syncthreads(); }
    mx = red[0]; __syncthreads();
    float sum = 0.0f;
    for (int i = t; i < K_; i += 256) { float e = expf(sd[i] - mx); sd[i] = e; sum += e; }
    red[t] = sum; __syncthreads();
    for (int o = 128; o > 0; o >>= 1) { if (t < o) red[t] += red[t + o]; __syncthreads(); }
    float inv = 1.0f / red[0];
    for (int i = t; i < K_; i += 256) p[i] = sd[i] * inv;
}

// ---------------- attn_avg = mean over heads -> d_out[32768:] ---------------
__global__ void k_avg(float* __restrict__ out2) {
    int idx = blockIdx.x * blockDim.x + threadIdx.x;  // 131072 total
    int b = idx >> 12, j = idx & 4095;
    float s = 0.0f;
#pragma unroll
    for (int h = 0; h < H_; h++) s += g_attn[((size_t)b * H_ + h) * K_ + j];
    out2[(size_t)b * K_ + j] = s * 0.125f;
}

// ---------------- ctx partials: attn[b,h,:] @ v[:,h,:] over j-split ---------
__global__ void k_ctxpart() {
    int h  = blockIdx.x;       // 8
    int sp = blockIdx.y;       // 16
    int jbase = sp * (K_ / NSPLIT);   // 256 j per split
    __shared__ float As[32][36];    // [j][b]
    __shared__ float Bs[32][128];   // [j][d]
    int t = threadIdx.x;
    float acc[4][4] = {};
    int rm = (t >> 5) * 4, rn = (t & 31) * 4;
    int ab = t >> 3, ajq = (t & 7) * 4;

    for (int k0 = 0; k0 < K_ / NSPLIT; k0 += 32) {
        float4 av = *(const float4*)(g_attn + ((size_t)ab * H_ + h) * K_ + jbase + k0 + ajq);
        As[ajq+0][ab]=av.x; As[ajq+1][ab]=av.y; As[ajq+2][ab]=av.z; As[ajq+3][ab]=av.w;
#pragma unroll
        for (int p = 0; p < 4; p++) {
            int id = t + p * 256;
            int jr = id >> 5, dc = (id & 31) * 4;
            *(float4*)&Bs[jr][dc] =
                *(const float4*)(g_vproj + (size_t)(jbase + k0 + jr) * D_ + h * HD_ + dc);
        }
        __syncthreads();
#pragma unroll
        for (int kk = 0; kk < 32; kk++) {
            float a[4], b[4];
            *(float4*)&a[0] = *(const float4*)&As[kk][rm];
            *(float4*)&b[0] = *(const float4*)&Bs[kk][rn];
#pragma unroll
            for (int i = 0; i < 4; i++)
#pragma unroll
                for (int j = 0; j < 4; j++)
                    acc[i][j] += a[i] * b[j];
        }
        __syncthreads();
    }
#pragma unroll
    for (int i = 0; i < 4; i++)
#pragma unroll
        for (int j = 0; j < 4; j++)
            g_ctx_part[((size_t)sp * B_ + rm + i) * D_ + h * HD_ + rn + j] = acc[i][j];
}

__global__ void k_ctxred() {
    int i = blockIdx.x * blockDim.x + threadIdx.x;  // 32768
    float s = 0.0f;
#pragma unroll
    for (int sp = 0; sp < NSPLIT; sp++) s += g_ctx_part[(size_t)sp * B_ * D_ + i];
    g_ctx[i] = s;
}

// ---------------- launch (fork/join stream DAG, graph-capturable) ----------
extern "C" void kernel_launch(void* const* d_in, const int* in_sizes, int n_in,
                              void* d_out, int out_size) {
    const float* query  = (const float*)d_in[0];
    const float* buffer = (const float*)d_in[1];
    const float* prio   = (const float*)d_in[2];
    const float* Wq     = (const float*)d_in[3];
    const float* bq     = (const float*)d_in[4];
    const float* Wk     = (const float*)d_in[5];
    const float* bk     = (const float*)d_in[6];
    const float* Wv     = (const float*)d_in[7];
    const float* bv     = (const float*)d_in[8];
    const float* Wo     = (const float*)d_in[9];
    const float* bo     = (const float*)d_in[10];
    float* out = (float*)d_out;   // [0,32768): retrieved, [32768,163840): attn_avg

    // Lazily created ONCE on the first (uncaptured correctness) call and
    // reused forever — so all driver-side allocations happen before the
    // harness's pre-capture memory baseline and nothing is allocated during
    // capture or leaked after graph teardown. The launch sequence below is
    // identical on every call.
    static cudaStream_t s2 = nullptr, s3 = nullptr, s4 = nullptr;
    static cudaEvent_t eFork = nullptr, eQdone = nullptr, eMain = nullptr,
                       eKdone = nullptr, eVdone = nullptr, eAttn = nullptr;
    if (s2 == nullptr) {
        cudaStreamCreateWithFlags(&s2, cudaStreamNonBlocking);
        cudaStreamCreateWithFlags(&s3, cudaStreamNonBlocking);
        cudaStreamCreateWithFlags(&s4, cudaStreamNonBlocking);
        cudaEventCreateWithFlags(&eFork,  cudaEventDisableTiming);
        cudaEventCreateWithFlags(&eQdone, cudaEventDisableTiming);
        cudaEventCreateWithFlags(&eMain,  cudaEventDisableTiming);
        cudaEventCreateWithFlags(&eKdone, cudaEventDisableTiming);
        cudaEventCreateWithFlags(&eVdone, cudaEventDisableTiming);
        cudaEventCreateWithFlags(&eAttn,  cudaEventDisableTiming);
        cudaFuncSetAttribute(k_kvproj_mma, cudaFuncAttributeMaxDynamicSharedMemorySize,
                             KV_SMEM_BYTES);
    }

    // ---- fork s2: weight pre-convert + q projection (independent of selection)
    cudaEventRecord(eFork, 0);
    cudaStreamWaitEvent(s2, eFork, 0);
    k_cvtW<<<dim3(32, 32, 2), dim3(32, 8), 0, s2>>>(Wk, Wv);
    k_gemm32s<<<dim3(8, GSPLIT), 256, 0, s2>>>(query, Wq, 0);
    k_gemmred<<<128, 256, 0, s2>>>(bq, nullptr, 0);
    cudaEventRecord(eQdone, s2);

    // ---- main stream: selection chain + gather
    k_zero16<<<64, 256>>>();
    k_hist16<<<64, 256>>>(prio);
    k_findbin<<<1, 1024>>>();
    k_compact16<<<64, 256>>>(prio);
    k_selfin48<<<1, 256>>>();
    k_rank<<<K_ / 8, 256>>>();
    k_gatherA<<<K_, 256>>>(buffer);

    // join s2 (kvproj needs g_WkH/g_WvH; scores later needs g_qproj)
    cudaStreamWaitEvent(0, eQdone, 0);
    cudaEventRecord(eMain, 0);

    // K projection (main) CONCURRENT with V projection (s4)
    cudaStreamWaitEvent(s4, eMain, 0);
    k_kvproj_mma<<<dim3(8, 32), 256, KV_SMEM_BYTES, s4>>>(bv, 1);
    cudaEventRecord(eVdone, s4);

    k_kvproj_mma<<<dim3(8, 32), 256, KV_SMEM_BYTES>>>(bk, 0);
    cudaEventRecord(eKdone, 0);

    // ---- fork s3: scores -> softmax -> avg (needs kproj + qproj only)
    cudaStreamWaitEvent(s3, eKdone, 0);
    k_scores<<<dim3(32, 8), 256, 0, s3>>>();
    k_softmax<<<256, 256, 0, s3>>>();
    k_avg<<<512, 256, 0, s3>>>(out + B_ * D_);
    cudaEventRecord(eAttn, s3);

    // join s3 + s4; ctx needs attn + vproj
    cudaStreamWaitEvent(0, eAttn, 0);
    cudaStreamWaitEvent(0, eVdone, 0);
    k_ctxpart<<<dim3(8, NSPLIT), 256>>>();
    k_ctxred<<<128, 256>>>();
    k_gemm32s<<<dim3(8, GSPLIT), 256>>>(nullptr, Wo, 1);   // output projection
    k_gemmred<<<128, 256>>>(bo, out, 1);
}